// round 2
// baseline (speedup 1.0000x reference)
#include <cuda_runtime.h>
#include <math.h>

// ---------------------------------------------------------------------------
// Problem constants (fixed for this problem instance)
//   B=4, L=1024, DH=2048, D=128, HQ=16, HK=HV=4, H=16, K=4
//   rows = B*L = 4096
// ---------------------------------------------------------------------------

#define ROWS 4096
#define DH_  2048
#define DHEAD 128
#define NH   16
#define NHK  4
#define SEQ  1024

// Scratch (device globals: allocation-free rule)
__device__ float g_xq[ROWS * DH_];        // X @ Wq
__device__ float g_xk[ROWS * 512];        // X @ Wk
__device__ float g_xv[ROWS * 512];        // X @ Wv
__device__ float g_xg[ROWS * DH_];        // X @ Wg (gate)
__device__ float g_q [ROWS * DH_];        // post conv+silu+l2norm, scaled
__device__ float g_k [ROWS * 512];
__device__ float g_v [ROWS * 512];
__device__ float g_beta[ROWS * NH];
__device__ float g_gd  [ROWS * NH];       // log decay g
__device__ float g_o [ROWS * DH_];        // recurrence output [row][h][d]
__device__ float g_of[ROWS * DH_];        // after gated rmsnorm

// ---------------------------------------------------------------------------
// SGEMM: C[M,N] = A[M,K] * B[K,N], all row-major, fp32.
// 128x128 tile, BK=16, 256 threads, 8x8 microtile. M%128==0, N%128==0, K%16==0.
// ---------------------------------------------------------------------------
__global__ __launch_bounds__(256) void sgemm128(
    const float* __restrict__ A, const float* __restrict__ B,
    float* __restrict__ C, int M, int N, int K)
{
    __shared__ __align__(16) float As[16][128];
    __shared__ __align__(16) float Bs[16][128];

    const int tid  = threadIdx.x;
    const int brow = blockIdx.y * 128;
    const int bcol = blockIdx.x * 128;
    const int tr   = (tid >> 4) << 3;   // 16x16 thread grid, 8 rows each
    const int tc   = (tid & 15) << 3;

    float acc[8][8];
    #pragma unroll
    for (int i = 0; i < 8; i++)
        #pragma unroll
        for (int j = 0; j < 8; j++) acc[i][j] = 0.f;

    const float* Aptr = A + (size_t)brow * K;
    const float* Bptr = B + bcol;

    for (int kt = 0; kt < K; kt += 16) {
        #pragma unroll
        for (int it = 0; it < 2; it++) {
            int a  = tid + it * 256;          // 0..511 (float4 index)
            int ar = a >> 2, ac = (a & 3) << 2;
            float4 av = *(const float4*)(Aptr + (size_t)ar * K + kt + ac);
            As[ac + 0][ar] = av.x; As[ac + 1][ar] = av.y;
            As[ac + 2][ar] = av.z; As[ac + 3][ar] = av.w;
            int br = a >> 5, bc = (a & 31) << 2;
            *(float4*)(&Bs[br][bc]) = *(const float4*)(Bptr + (size_t)(kt + br) * N + bc);
        }
        __syncthreads();
        #pragma unroll
        for (int kk = 0; kk < 16; kk++) {
            float a0[8], b0[8];
            *(float4*)(a0)     = *(const float4*)&As[kk][tr];
            *(float4*)(a0 + 4) = *(const float4*)&As[kk][tr + 4];
            *(float4*)(b0)     = *(const float4*)&Bs[kk][tc];
            *(float4*)(b0 + 4) = *(const float4*)&Bs[kk][tc + 4];
            #pragma unroll
            for (int i = 0; i < 8; i++)
                #pragma unroll
                for (int j = 0; j < 8; j++)
                    acc[i][j] = fmaf(a0[i], b0[j], acc[i][j]);
        }
        __syncthreads();
    }
    #pragma unroll
    for (int i = 0; i < 8; i++) {
        float* cp = C + (size_t)(brow + tr + i) * N + bcol + tc;
        *(float4*)(cp)     = make_float4(acc[i][0], acc[i][1], acc[i][2], acc[i][3]);
        *(float4*)(cp + 4) = make_float4(acc[i][4], acc[i][5], acc[i][6], acc[i][7]);
    }
}

// ---------------------------------------------------------------------------
// beta = sigmoid(X @ Wb), g = -exp(A_log) * softplus(X @ Wgk + dt_bias)
// One block per row; 256 threads, 32 outputs (16 beta + 16 g), 8 threads each.
// ---------------------------------------------------------------------------
__global__ __launch_bounds__(256) void betag_kernel(
    const float* __restrict__ x, const float* __restrict__ Wb,
    const float* __restrict__ Wgk, const float* __restrict__ A_log,
    const float* __restrict__ dt_bias)
{
    __shared__ float xs[DH_];
    const int row = blockIdx.x;
    for (int i = threadIdx.x; i < DH_; i += 256) xs[i] = x[(size_t)row * DH_ + i];
    __syncthreads();

    const int o     = threadIdx.x >> 3;   // 0..31
    const int lane8 = threadIdx.x & 7;
    const int h     = o & 15;
    const float* W  = (o < 16) ? Wb : Wgk;

    float s = 0.f;
    for (int c = lane8; c < DH_; c += 8) s += xs[c] * W[c * NH + h];
    #pragma unroll
    for (int off = 4; off > 0; off >>= 1)
        s += __shfl_down_sync(0xffffffffu, s, off, 8);

    if (lane8 == 0) {
        if (o < 16) {
            g_beta[row * NH + h] = 1.f / (1.f + expf(-s));
        } else {
            float xg = s + dt_bias[h];
            float sp = (xg > 15.f) ? xg : log1pf(expf(xg));
            g_gd[row * NH + h] = -expf(A_log[h]) * sp;
        }
    }
}

// ---------------------------------------------------------------------------
// Causal depthwise conv (K=4) + SiLU (+ optional per-head L2 norm * scale).
// grid (ROWS, nheads), 128 threads (one per d within head).
// ---------------------------------------------------------------------------
__global__ __launch_bounds__(128) void conv_kernel(
    const float* __restrict__ in, const float* __restrict__ w,
    float* __restrict__ out, int C, int do_l2, float scale)
{
    const int row = blockIdx.x;
    const int c   = blockIdx.y * DHEAD + threadIdx.x;
    const int l   = row & (SEQ - 1);

    float acc = 0.f;
    #pragma unroll
    for (int j = 0; j < 4; j++) {
        int sl = l + j - 3;
        if (sl >= 0) acc += in[(size_t)(row + j - 3) * C + c] * w[c * 4 + j];
    }
    float y = acc / (1.f + expf(-acc));   // silu

    if (do_l2) {
        __shared__ float sm[4];
        float ss = y * y;
        #pragma unroll
        for (int off = 16; off > 0; off >>= 1)
            ss += __shfl_xor_sync(0xffffffffu, ss, off);
        if ((threadIdx.x & 31) == 0) sm[threadIdx.x >> 5] = ss;
        __syncthreads();
        float tot = sm[0] + sm[1] + sm[2] + sm[3];
        y *= rsqrtf(tot + 1e-6f) * scale;
    }
    out[(size_t)row * C + c] = y;
}

// ---------------------------------------------------------------------------
// Gated delta-rule recurrence. One CTA per (b,h) = 64 CTAs, 128 threads.
// Thread t owns value-column t; full key-dim state S[128] in registers.
//   S = S * exp(g); vres = v[t] - sum_d k[d]*S[d];
//   S += (beta*vres)*k;  o[t] = sum_d q[d]*S[d]
// Next-step q/k/v/g/beta prefetched one step ahead (double-buffered smem).
// ---------------------------------------------------------------------------
__global__ __launch_bounds__(128) void recurrence_kernel()
{
    __shared__ __align__(16) float ks[2][DHEAD];
    __shared__ __align__(16) float qs[2][DHEAD];

    const int b  = blockIdx.x >> 4;
    const int h  = blockIdx.x & 15;
    const int kh = h >> 2;                 // GQA: 4 q-heads share one k/v head
    const int t  = threadIdx.x;

    float S[DHEAD];
    #pragma unroll
    for (int d = 0; d < DHEAD; d++) S[d] = 0.f;

    const float* qp = g_q    + ((size_t)(b * SEQ) * NH  + h ) * DHEAD + t;  // stride 2048
    const float* kp = g_k    + ((size_t)(b * SEQ) * NHK + kh) * DHEAD + t;  // stride 512
    const float* vp = g_v    + ((size_t)(b * SEQ) * NHK + kh) * DHEAD + t;
    const float* gp = g_gd   +  (size_t)(b * SEQ) * NH + h;                  // stride 16
    const float* bp = g_beta +  (size_t)(b * SEQ) * NH + h;
    float*       op = g_o    + ((size_t)(b * SEQ) * NH  + h ) * DHEAD + t;

    // preload step 0
    float kcur = kp[0], qcur = qp[0], vcur = vp[0], gcur = gp[0], bcur = bp[0];
    ks[0][t] = kcur; qs[0][t] = qcur;
    __syncthreads();

    for (int l = 0; l < SEQ; l++) {
        const int cur = l & 1, nxt = cur ^ 1;
        // prefetch l+1
        float knx = 0.f, qnx = 0.f, vnx = 0.f, gnx = 0.f, bnx = 0.f;
        if (l + 1 < SEQ) {
            knx = kp[(size_t)(l + 1) * 512];
            qnx = qp[(size_t)(l + 1) * 2048];
            vnx = vp[(size_t)(l + 1) * 512];
            gnx = gp[(size_t)(l + 1) * NH];
            bnx = bp[(size_t)(l + 1) * NH];
        }

        const float eg = expf(gcur);
        const float4* k4p = reinterpret_cast<const float4*>(ks[cur]);
        const float4* q4p = reinterpret_cast<const float4*>(qs[cur]);

        float kv0 = 0.f, kv1 = 0.f, kv2 = 0.f, kv3 = 0.f;
        #pragma unroll
        for (int d4 = 0; d4 < 32; d4++) {
            float4 k4 = k4p[d4];
            int d = d4 << 2;
            S[d + 0] *= eg; kv0 = fmaf(k4.x, S[d + 0], kv0);
            S[d + 1] *= eg; kv1 = fmaf(k4.y, S[d + 1], kv1);
            S[d + 2] *= eg; kv2 = fmaf(k4.z, S[d + 2], kv2);
            S[d + 3] *= eg; kv3 = fmaf(k4.w, S[d + 3], kv3);
        }
        const float cc = bcur * (vcur - ((kv0 + kv1) + (kv2 + kv3)));

        float qo0 = 0.f, qo1 = 0.f, qo2 = 0.f, qo3 = 0.f;
        #pragma unroll
        for (int d4 = 0; d4 < 32; d4++) {
            float4 k4 = k4p[d4];
            float4 q4 = q4p[d4];
            int d = d4 << 2;
            S[d + 0] = fmaf(k4.x, cc, S[d + 0]); qo0 = fmaf(q4.x, S[d + 0], qo0);
            S[d + 1] = fmaf(k4.y, cc, S[d + 1]); qo1 = fmaf(q4.y, S[d + 1], qo1);
            S[d + 2] = fmaf(k4.z, cc, S[d + 2]); qo2 = fmaf(q4.z, S[d + 2], qo2);
            S[d + 3] = fmaf(k4.w, cc, S[d + 3]); qo3 = fmaf(q4.w, S[d + 3], qo3);
        }
        op[(size_t)l * 2048] = (qo0 + qo1) + (qo2 + qo3);

        __syncthreads();                  // everyone done reading ks/qs[cur]
        ks[nxt][t] = knx; qs[nxt][t] = qnx;
        vcur = vnx; gcur = gnx; bcur = bnx;
        __syncthreads();                  // next buffer ready
    }
}

// ---------------------------------------------------------------------------
// FusedRMSNormGated: o * rsqrt(mean(o^2)+1e-5) * w[d] * silu(gate)
// grid (ROWS, NH), 128 threads.
// ---------------------------------------------------------------------------
__global__ __launch_bounds__(128) void rmsgate_kernel(
    const float* __restrict__ xg, const float* __restrict__ w)
{
    const int row = blockIdx.x;
    const int h   = blockIdx.y;
    const int t   = threadIdx.x;

    const size_t idx = (size_t)(row * NH + h) * DHEAD + t;
    float o = g_o[idx];

    float ss = o * o;
    #pragma unroll
    for (int off = 16; off > 0; off >>= 1)
        ss += __shfl_xor_sync(0xffffffffu, ss, off);
    __shared__ float sm[4];
    if ((t & 31) == 0) sm[t >> 5] = ss;
    __syncthreads();
    float tot = sm[0] + sm[1] + sm[2] + sm[3];
    float r = rsqrtf(tot * (1.f / 128.f) + 1e-5f);

    float gate = xg[(size_t)row * DH_ + h * DHEAD + t];
    float sg   = gate / (1.f + expf(-gate));
    g_of[(size_t)row * DH_ + h * DHEAD + t] = o * r * w[t] * sg;
}

// ---------------------------------------------------------------------------
// Launch
// ---------------------------------------------------------------------------
extern "C" void kernel_launch(void* const* d_in, const int* in_sizes, int n_in,
                              void* d_out, int out_size)
{
    (void)in_sizes; (void)n_in; (void)out_size;
    const float* x     = (const float*)d_in[0];
    const float* Wq    = (const float*)d_in[1];
    const float* Wk    = (const float*)d_in[2];
    const float* Wv    = (const float*)d_in[3];
    const float* Wb    = (const float*)d_in[4];
    const float* Wgk   = (const float*)d_in[5];
    const float* A_log = (const float*)d_in[6];
    const float* dt_b  = (const float*)d_in[7];
    const float* convq = (const float*)d_in[8];
    const float* convk = (const float*)d_in[9];
    const float* convv = (const float*)d_in[10];
    const float* Wg    = (const float*)d_in[11];
    const float* onw   = (const float*)d_in[12];
    const float* Wo    = (const float*)d_in[13];
    float* out = (float*)d_out;

    float *p_xq, *p_xk, *p_xv, *p_xg, *p_q, *p_k, *p_v, *p_of;
    cudaGetSymbolAddress((void**)&p_xq, g_xq);
    cudaGetSymbolAddress((void**)&p_xk, g_xk);
    cudaGetSymbolAddress((void**)&p_xv, g_xv);
    cudaGetSymbolAddress((void**)&p_xg, g_xg);
    cudaGetSymbolAddress((void**)&p_q,  g_q);
    cudaGetSymbolAddress((void**)&p_k,  g_k);
    cudaGetSymbolAddress((void**)&p_v,  g_v);
    cudaGetSymbolAddress((void**)&p_of, g_of);

    // 1) projections
    sgemm128<<<dim3(16, 32), 256>>>(x, Wq, p_xq, ROWS, 2048, DH_);
    sgemm128<<<dim3( 4, 32), 256>>>(x, Wk, p_xk, ROWS,  512, DH_);
    sgemm128<<<dim3( 4, 32), 256>>>(x, Wv, p_xv, ROWS,  512, DH_);
    sgemm128<<<dim3(16, 32), 256>>>(x, Wg, p_xg, ROWS, 2048, DH_);
    betag_kernel<<<ROWS, 256>>>(x, Wb, Wgk, A_log, dt_b);

    // 2) conv + silu (+ l2 norm for q,k; q also scaled by D^-0.5)
    conv_kernel<<<dim3(ROWS, 16), 128>>>(p_xq, convq, p_q, 2048, 1, 0.08838834764831845f);
    conv_kernel<<<dim3(ROWS,  4), 128>>>(p_xk, convk, p_k,  512, 1, 1.f);
    conv_kernel<<<dim3(ROWS,  4), 128>>>(p_xv, convv, p_v,  512, 0, 1.f);

    // 3) sequential recurrence
    recurrence_kernel<<<64, 128>>>();

    // 4) gated rmsnorm
    rmsgate_kernel<<<dim3(ROWS, 16), 128>>>(p_xg, onw);

    // 5) output projection
    sgemm128<<<dim3(16, 32), 256>>>(p_of, Wo, out, ROWS, 2048, DH_);
}

// round 4
// speedup vs baseline: 1.6800x; 1.6800x over previous
#include <cuda_runtime.h>
#include <cuda_bf16.h>
#include <math.h>
#include <stdint.h>

// ---------------------------------------------------------------------------
// Problem constants: B=4, L=1024, DH=2048, D=128, HQ=16, HK=HV=4, H=16, K=4
// ---------------------------------------------------------------------------
#define ROWS 4096
#define DH_  2048
#define DHEAD 128
#define NH   16
#define NHK  4
#define SEQ  1024

// ---------------- device scratch (allocation-free rule) --------------------
__device__ float g_xq[ROWS * DH_];
__device__ float g_xk[ROWS * 512];
__device__ float g_xv[ROWS * 512];
__device__ float g_xg[ROWS * DH_];
__device__ float g_q [ROWS * DH_];
__device__ float g_k [ROWS * 512];
__device__ float g_v [ROWS * 512];
__device__ float g_beta[ROWS * NH];
__device__ float g_gd  [ROWS * NH];
__device__ float g_o [ROWS * DH_];

__device__ __align__(256) __nv_bfloat16 g_xhi[ROWS * DH_];
__device__ __align__(256) __nv_bfloat16 g_xlo[ROWS * DH_];
__device__ __align__(256) __nv_bfloat16 g_ofhi[ROWS * DH_];
__device__ __align__(256) __nv_bfloat16 g_oflo[ROWS * DH_];
__device__ __align__(256) __nv_bfloat16 g_wqt_hi[DH_ * DH_];
__device__ __align__(256) __nv_bfloat16 g_wqt_lo[DH_ * DH_];
__device__ __align__(256) __nv_bfloat16 g_wgt_hi[DH_ * DH_];
__device__ __align__(256) __nv_bfloat16 g_wgt_lo[DH_ * DH_];
__device__ __align__(256) __nv_bfloat16 g_wot_hi[DH_ * DH_];
__device__ __align__(256) __nv_bfloat16 g_wot_lo[DH_ * DH_];
__device__ __align__(256) __nv_bfloat16 g_wkt_hi[512 * DH_];
__device__ __align__(256) __nv_bfloat16 g_wkt_lo[512 * DH_];
__device__ __align__(256) __nv_bfloat16 g_wvt_hi[512 * DH_];
__device__ __align__(256) __nv_bfloat16 g_wvt_lo[512 * DH_];

// ---------------------------------------------------------------------------
// PTX helpers (baseline ISA only — no sm_103a features)
// ---------------------------------------------------------------------------
__device__ __forceinline__ uint32_t smem_to_u32(const void* p) {
    uint32_t a;
    asm("{ .reg .u64 t; cvta.to.shared.u64 t, %1; cvt.u32.u64 %0, t; }"
        : "=r"(a) : "l"(p));
    return a;
}
__device__ __forceinline__ void cp16(uint32_t s, const void* g) {
    asm volatile("cp.async.cg.shared.global [%0], [%1], 16;"
                 :: "r"(s), "l"(g) : "memory");
}
#define CP_COMMIT() asm volatile("cp.async.commit_group;" ::: "memory")

#define LDSM4(d, addr) \
    asm volatile("ldmatrix.sync.aligned.m8n8.x4.shared.b16 {%0,%1,%2,%3}, [%4];" \
        : "=r"((d)[0]), "=r"((d)[1]), "=r"((d)[2]), "=r"((d)[3]) : "r"(addr))

#define MMA16816(c, a, b) \
    asm volatile("mma.sync.aligned.m16n8k16.row.col.f32.bf16.bf16.f32 " \
        "{%0,%1,%2,%3}, {%4,%5,%6,%7}, {%8,%9}, {%0,%1,%2,%3};" \
        : "+f"((c)[0]), "+f"((c)[1]), "+f"((c)[2]), "+f"((c)[3]) \
        : "r"((a)[0]), "r"((a)[1]), "r"((a)[2]), "r"((a)[3]), \
          "r"((b)[0]), "r"((b)[1]))

// ---------------------------------------------------------------------------
// fp32 -> bf16 hi/lo split (elementwise, 2 elems/thread)
// ---------------------------------------------------------------------------
__global__ __launch_bounds__(256) void hilo_kernel(
    const float* __restrict__ in, __nv_bfloat16* __restrict__ hi,
    __nv_bfloat16* __restrict__ lo, int n2)
{
    int i = blockIdx.x * 256 + threadIdx.x;
    if (i >= n2) return;
    float2 v = ((const float2*)in)[i];
    __nv_bfloat16 h0 = __float2bfloat16_rn(v.x);
    __nv_bfloat16 h1 = __float2bfloat16_rn(v.y);
    __nv_bfloat16 l0 = __float2bfloat16_rn(v.x - __bfloat162float(h0));
    __nv_bfloat16 l1 = __float2bfloat16_rn(v.y - __bfloat162float(h1));
    ((__nv_bfloat162*)hi)[i] = __halves2bfloat162(h0, h1);
    ((__nv_bfloat162*)lo)[i] = __halves2bfloat162(l0, l1);
}

// ---------------------------------------------------------------------------
// W [K,N] fp32 -> Wt [N,K] bf16 hi/lo (tiled transpose)
// ---------------------------------------------------------------------------
__global__ __launch_bounds__(256) void transpose_hilo(
    const float* __restrict__ W, __nv_bfloat16* __restrict__ Thi,
    __nv_bfloat16* __restrict__ Tlo, int K, int N)
{
    __shared__ float t[32][33];
    const int bx = blockIdx.x * 32;   // N
    const int by = blockIdx.y * 32;   // K
    const int tx = threadIdx.x & 31, ty = threadIdx.x >> 5;
    #pragma unroll
    for (int i = 0; i < 32; i += 8)
        t[ty + i][tx] = W[(size_t)(by + ty + i) * N + bx + tx];
    __syncthreads();
    #pragma unroll
    for (int i = 0; i < 32; i += 8) {
        float v = t[tx][ty + i];
        __nv_bfloat16 h = __float2bfloat16_rn(v);
        size_t o = (size_t)(bx + ty + i) * K + by + tx;
        Thi[o] = h;
        Tlo[o] = __float2bfloat16_rn(v - __bfloat162float(h));
    }
}

// ---------------------------------------------------------------------------
// bf16 mma.sync GEMM with hi/lo compensation (hh + hl + lh):
//   C[M,N] = (Ahi+Alo)[M,K] @ (Bhi+Blo)[N,K]^T, fp32 accumulate
// BM=BN=128, BK=64. 256 threads = 8 warps (2 m x 4 n), warp tile 64x32.
// 3-stage cp.async pipeline. XOR-swizzled smem, ldmatrix.x4 operand loads.
// ---------------------------------------------------------------------------
#define ST_BYTES 65536          // per stage: Ahi 16K | Alo 16K | Bhi 16K | Blo 16K
#define SM_GEMM  (3 * ST_BYTES)

__global__ __launch_bounds__(256) void gemm_mma(
    const __nv_bfloat16* __restrict__ Ahi, const __nv_bfloat16* __restrict__ Alo,
    const __nv_bfloat16* __restrict__ Bhi, const __nv_bfloat16* __restrict__ Blo,
    float* __restrict__ C, int N, int K)
{
    extern __shared__ char smem[];
    const uint32_t sb = smem_to_u32(smem);
    const int tid  = threadIdx.x;
    const int lane = tid & 31;
    const int wid  = tid >> 5;
    const int wm   = wid & 1;        // 0..1
    const int wn   = wid >> 1;       // 0..3
    const int brow = blockIdx.y * 128;
    const int bcol = blockIdx.x * 128;
    const size_t K2 = (size_t)K * 2;   // bytes per row

    // per-thread cp.async descriptors: 4 x 16B per 16KB buffer
    uint32_t swo[4];
    size_t   ga[4], gb[4];
    #pragma unroll
    for (int i = 0; i < 4; i++) {
        int c  = tid + (i << 8);       // 0..1023
        int r  = c >> 3;               // row 0..127
        int ch = c & 7;                // 16B chunk 0..7
        swo[i] = (uint32_t)(r * 128 + ((ch ^ (r & 7)) << 4));
        ga[i]  = (size_t)(brow + r) * K2 + (size_t)(ch << 4);
        gb[i]  = (size_t)(bcol + r) * K2 + (size_t)(ch << 4);
    }

    const int NK = K >> 6;

    // pipeline prologue: stages 0,1
    #pragma unroll
    for (int pf = 0; pf < 2; pf++) {
        uint32_t s0 = sb + pf * ST_BYTES;
        size_t ko = (size_t)pf << 7;   // kt*128 bytes
        #pragma unroll
        for (int i = 0; i < 4; i++) {
            cp16(s0 +     0 + swo[i], (const char*)Ahi + ga[i] + ko);
            cp16(s0 + 16384 + swo[i], (const char*)Alo + ga[i] + ko);
            cp16(s0 + 32768 + swo[i], (const char*)Bhi + gb[i] + ko);
            cp16(s0 + 49152 + swo[i], (const char*)Blo + gb[i] + ko);
        }
        CP_COMMIT();
    }

    float acc[4][4][4];
    #pragma unroll
    for (int mi = 0; mi < 4; mi++)
        #pragma unroll
        for (int ni = 0; ni < 4; ni++)
            #pragma unroll
            for (int j = 0; j < 4; j++) acc[mi][ni][j] = 0.f;

    int st_load = 2, st_cmp = 0;
    for (int kt = 0; kt < NK; kt++) {
        if (kt + 2 < NK) {
            uint32_t s0 = sb + st_load * ST_BYTES;
            size_t ko = (size_t)(kt + 2) << 7;
            #pragma unroll
            for (int i = 0; i < 4; i++) {
                cp16(s0 +     0 + swo[i], (const char*)Ahi + ga[i] + ko);
                cp16(s0 + 16384 + swo[i], (const char*)Alo + ga[i] + ko);
                cp16(s0 + 32768 + swo[i], (const char*)Bhi + gb[i] + ko);
                cp16(s0 + 49152 + swo[i], (const char*)Blo + gb[i] + ko);
            }
            CP_COMMIT();
            if (++st_load == 3) st_load = 0;
        }
        // wait until current stage's group has landed
        int ahead = NK - 1 - kt; if (ahead > 2) ahead = 2;
        if (ahead == 2)      asm volatile("cp.async.wait_group 2;" ::: "memory");
        else if (ahead == 1) asm volatile("cp.async.wait_group 1;" ::: "memory");
        else                 asm volatile("cp.async.wait_group 0;" ::: "memory");
        __syncthreads();

        const uint32_t sa = sb + st_cmp * ST_BYTES;
        #pragma unroll
        for (int ks = 0; ks < 4; ks++) {
            uint32_t ah[4][4], al[4][4];
            const int chA = (ks << 1) + (lane >> 4);
            #pragma unroll
            for (int mi = 0; mi < 4; mi++) {
                int r = wm * 64 + mi * 16 + (lane & 15);
                uint32_t ad = sa + (uint32_t)(r * 128 + ((chA ^ (r & 7)) << 4));
                LDSM4(ah[mi], ad);
                LDSM4(al[mi], ad + 16384);
            }
            uint32_t bh[4][2], bl[4][2];
            #pragma unroll
            for (int nb = 0; nb < 2; nb++) {
                int r = wn * 32 + nb * 16 + (lane & 15);
                uint32_t bd = sa + 32768u + (uint32_t)(r * 128 + ((chA ^ (r & 7)) << 4));
                uint32_t d[4];
                LDSM4(d, bd);
                bh[2*nb][0] = d[0]; bh[2*nb][1] = d[2];
                bh[2*nb+1][0] = d[1]; bh[2*nb+1][1] = d[3];
                LDSM4(d, bd + 16384);
                bl[2*nb][0] = d[0]; bl[2*nb][1] = d[2];
                bl[2*nb+1][0] = d[1]; bl[2*nb+1][1] = d[3];
            }
            #pragma unroll
            for (int mi = 0; mi < 4; mi++)
                #pragma unroll
                for (int ni = 0; ni < 4; ni++) {
                    MMA16816(acc[mi][ni], ah[mi], bh[ni]);
                    MMA16816(acc[mi][ni], ah[mi], bl[ni]);
                    MMA16816(acc[mi][ni], al[mi], bh[ni]);
                }
        }
        __syncthreads();
        if (++st_cmp == 3) st_cmp = 0;
    }

    // epilogue: fp32 stores
    #pragma unroll
    for (int mi = 0; mi < 4; mi++) {
        int r0 = brow + wm * 64 + mi * 16 + (lane >> 2);
        #pragma unroll
        for (int ni = 0; ni < 4; ni++) {
            int c0 = bcol + wn * 32 + ni * 8 + ((lane & 3) << 1);
            *(float2*)&C[(size_t)r0 * N + c0] =
                make_float2(acc[mi][ni][0], acc[mi][ni][1]);
            *(float2*)&C[(size_t)(r0 + 8) * N + c0] =
                make_float2(acc[mi][ni][2], acc[mi][ni][3]);
        }
    }
}

// ---------------------------------------------------------------------------
// beta = sigmoid(X @ Wb), g = -exp(A_log) * softplus(X @ Wgk + dt_bias)
// ---------------------------------------------------------------------------
__global__ __launch_bounds__(256) void betag_kernel(
    const float* __restrict__ x, const float* __restrict__ Wb,
    const float* __restrict__ Wgk, const float* __restrict__ A_log,
    const float* __restrict__ dt_bias)
{
    __shared__ float xs[DH_];
    const int row = blockIdx.x;
    for (int i = threadIdx.x; i < DH_; i += 256) xs[i] = x[(size_t)row * DH_ + i];
    __syncthreads();

    const int o     = threadIdx.x >> 3;
    const int lane8 = threadIdx.x & 7;
    const int h     = o & 15;
    const float* W  = (o < 16) ? Wb : Wgk;

    float s = 0.f;
    for (int c = lane8; c < DH_; c += 8) s += xs[c] * W[c * NH + h];
    #pragma unroll
    for (int off = 4; off > 0; off >>= 1)
        s += __shfl_down_sync(0xffffffffu, s, off, 8);

    if (lane8 == 0) {
        if (o < 16) {
            g_beta[row * NH + h] = 1.f / (1.f + expf(-s));
        } else {
            float xg = s + dt_bias[h];
            float sp = (xg > 15.f) ? xg : log1pf(expf(xg));
            g_gd[row * NH + h] = -expf(A_log[h]) * sp;
        }
    }
}

// ---------------------------------------------------------------------------
// Causal depthwise conv (K=4) + SiLU (+ optional L2 norm * scale)
// ---------------------------------------------------------------------------
__global__ __launch_bounds__(128) void conv_kernel(
    const float* __restrict__ in, const float* __restrict__ w,
    float* __restrict__ out, int C, int do_l2, float scale)
{
    const int row = blockIdx.x;
    const int c   = blockIdx.y * DHEAD + threadIdx.x;
    const int l   = row & (SEQ - 1);

    float acc = 0.f;
    #pragma unroll
    for (int j = 0; j < 4; j++) {
        int sl = l + j - 3;
        if (sl >= 0) acc += in[(size_t)(row + j - 3) * C + c] * w[c * 4 + j];
    }
    float y = acc / (1.f + expf(-acc));

    if (do_l2) {
        __shared__ float sm[4];
        float ss = y * y;
        #pragma unroll
        for (int off = 16; off > 0; off >>= 1)
            ss += __shfl_xor_sync(0xffffffffu, ss, off);
        if ((threadIdx.x & 31) == 0) sm[threadIdx.x >> 5] = ss;
        __syncthreads();
        float tot = sm[0] + sm[1] + sm[2] + sm[3];
        y *= rsqrtf(tot + 1e-6f) * scale;
    }
    out[(size_t)row * C + c] = y;
}

// ---------------------------------------------------------------------------
// Gated delta-rule recurrence with packed f32x2 FMAs.
// 64 CTAs (b,h), 128 threads; thread owns value-col t, state S[128] (64 pairs).
// ---------------------------------------------------------------------------
#define FMA2(d, a, b, c) \
    asm("fma.rn.f32x2 %0, %1, %2, %3;" : "=l"(d) : "l"(a), "l"(b), "l"(c))
#define MUL2(d, a, b) \
    asm("mul.rn.f32x2 %0, %1, %2;" : "=l"(d) : "l"(a), "l"(b))

__device__ __forceinline__ unsigned long long f2pack(float a, float b) {
    unsigned long long r;
    asm("mov.b64 %0, {%1, %2};" : "=l"(r)
        : "r"(__float_as_uint(a)), "r"(__float_as_uint(b)));
    return r;
}
__device__ __forceinline__ float f2sum(unsigned long long v) {
    uint32_t x, y;
    asm("mov.b64 {%0, %1}, %2;" : "=r"(x), "=r"(y) : "l"(v));
    return __uint_as_float(x) + __uint_as_float(y);
}

__global__ __launch_bounds__(128) void recurrence_kernel()
{
    __shared__ __align__(16) float ks[2][DHEAD];
    __shared__ __align__(16) float qs[2][DHEAD];

    const int b  = blockIdx.x >> 4;
    const int h  = blockIdx.x & 15;
    const int kh = h >> 2;
    const int t  = threadIdx.x;

    unsigned long long S2[64];
    #pragma unroll
    for (int d = 0; d < 64; d++) S2[d] = 0ull;

    const float* qp = g_q    + ((size_t)(b * SEQ) * NH  + h ) * DHEAD + t;
    const float* kp = g_k    + ((size_t)(b * SEQ) * NHK + kh) * DHEAD + t;
    const float* vp = g_v    + ((size_t)(b * SEQ) * NHK + kh) * DHEAD + t;
    const float* gp = g_gd   +  (size_t)(b * SEQ) * NH + h;
    const float* bp = g_beta +  (size_t)(b * SEQ) * NH + h;
    float*       op = g_o    + ((size_t)(b * SEQ) * NH  + h ) * DHEAD + t;

    float kcur = kp[0], qcur = qp[0];
    float vcur = vp[0], gcur = gp[0], bcur = bp[0];
    ks[0][t] = kcur; qs[0][t] = qcur;
    __syncthreads();

    for (int l = 0; l < SEQ; l++) {
        const int cur = l & 1, nxt = cur ^ 1;
        float knx = 0.f, qnx = 0.f, vnx = 0.f, gnx = 0.f, bnx = 0.f;
        if (l + 1 < SEQ) {
            knx = kp[(size_t)(l + 1) * 512];
            qnx = qp[(size_t)(l + 1) * 2048];
            vnx = vp[(size_t)(l + 1) * 512];
            gnx = gp[(size_t)(l + 1) * NH];
            bnx = bp[(size_t)(l + 1) * NH];
        }

        const float eg = expf(gcur);
        const unsigned long long eg2 = f2pack(eg, eg);
        const ulonglong2* k2p = reinterpret_cast<const ulonglong2*>(ks[cur]);
        const ulonglong2* q2p = reinterpret_cast<const ulonglong2*>(qs[cur]);

        unsigned long long kva = 0ull, kvb = 0ull;
        #pragma unroll
        for (int i = 0; i < 32; i++) {
            ulonglong2 kk = k2p[i];
            MUL2(S2[2 * i], S2[2 * i], eg2);
            FMA2(kva, kk.x, S2[2 * i], kva);
            MUL2(S2[2 * i + 1], S2[2 * i + 1], eg2);
            FMA2(kvb, kk.y, S2[2 * i + 1], kvb);
        }
        const float cc = bcur * (vcur - (f2sum(kva) + f2sum(kvb)));
        const unsigned long long cc2 = f2pack(cc, cc);

        unsigned long long qa = 0ull, qb = 0ull;
        #pragma unroll
        for (int i = 0; i < 32; i++) {
            ulonglong2 kk = k2p[i];
            ulonglong2 qq = q2p[i];
            FMA2(S2[2 * i], kk.x, cc2, S2[2 * i]);
            FMA2(qa, qq.x, S2[2 * i], qa);
            FMA2(S2[2 * i + 1], kk.y, cc2, S2[2 * i + 1]);
            FMA2(qb, qq.y, S2[2 * i + 1], qb);
        }
        op[(size_t)l * 2048] = f2sum(qa) + f2sum(qb);

        ks[nxt][t] = knx; qs[nxt][t] = qnx;
        __syncthreads();
        vcur = vnx; gcur = gnx; bcur = bnx;
    }
}

// ---------------------------------------------------------------------------
// FusedRMSNormGated; writes bf16 hi/lo for the final tensor-core GEMM.
// ---------------------------------------------------------------------------
__global__ __launch_bounds__(128) void rmsgate_kernel(
    const float* __restrict__ xg, const float* __restrict__ w)
{
    const int row = blockIdx.x;
    const int h   = blockIdx.y;
    const int t   = threadIdx.x;

    const size_t idx = (size_t)(row * NH + h) * DHEAD + t;
    float o = g_o[idx];

    float ss = o * o;
    #pragma unroll
    for (int off = 16; off > 0; off >>= 1)
        ss += __shfl_xor_sync(0xffffffffu, ss, off);
    __shared__ float sm[4];
    if ((t & 31) == 0) sm[t >> 5] = ss;
    __syncthreads();
    float tot = sm[0] + sm[1] + sm[2] + sm[3];
    float r = rsqrtf(tot * (1.f / 128.f) + 1e-5f);

    float gate = xg[(size_t)row * DH_ + h * DHEAD + t];
    float sg   = gate / (1.f + expf(-gate));
    float val  = o * r * w[t] * sg;

    size_t oo = (size_t)row * DH_ + h * DHEAD + t;
    __nv_bfloat16 hi = __float2bfloat16_rn(val);
    g_ofhi[oo] = hi;
    g_oflo[oo] = __float2bfloat16_rn(val - __bfloat162float(hi));
}

// ---------------------------------------------------------------------------
// Launch
// ---------------------------------------------------------------------------
extern "C" void kernel_launch(void* const* d_in, const int* in_sizes, int n_in,
                              void* d_out, int out_size)
{
    (void)in_sizes; (void)n_in; (void)out_size;
    const float* x     = (const float*)d_in[0];
    const float* Wq    = (const float*)d_in[1];
    const float* Wk    = (const float*)d_in[2];
    const float* Wv    = (const float*)d_in[3];
    const float* Wb    = (const float*)d_in[4];
    const float* Wgk   = (const float*)d_in[5];
    const float* A_log = (const float*)d_in[6];
    const float* dt_b  = (const float*)d_in[7];
    const float* convq = (const float*)d_in[8];
    const float* convk = (const float*)d_in[9];
    const float* convv = (const float*)d_in[10];
    const float* Wg    = (const float*)d_in[11];
    const float* onw   = (const float*)d_in[12];
    const float* Wo    = (const float*)d_in[13];
    float* out = (float*)d_out;

    cudaFuncSetAttribute(gemm_mma, cudaFuncAttributeMaxDynamicSharedMemorySize, SM_GEMM);

    float *p_xq, *p_xk, *p_xv, *p_xg, *p_q, *p_k, *p_v;
    __nv_bfloat16 *p_xhi, *p_xlo, *p_ofhi, *p_oflo;
    __nv_bfloat16 *p_wqh, *p_wql, *p_wkh, *p_wkl, *p_wvh, *p_wvl, *p_wgh, *p_wgl, *p_woh, *p_wol;
    cudaGetSymbolAddress((void**)&p_xq, g_xq);
    cudaGetSymbolAddress((void**)&p_xk, g_xk);
    cudaGetSymbolAddress((void**)&p_xv, g_xv);
    cudaGetSymbolAddress((void**)&p_xg, g_xg);
    cudaGetSymbolAddress((void**)&p_q,  g_q);
    cudaGetSymbolAddress((void**)&p_k,  g_k);
    cudaGetSymbolAddress((void**)&p_v,  g_v);
    cudaGetSymbolAddress((void**)&p_xhi, g_xhi);
    cudaGetSymbolAddress((void**)&p_xlo, g_xlo);
    cudaGetSymbolAddress((void**)&p_ofhi, g_ofhi);
    cudaGetSymbolAddress((void**)&p_oflo, g_oflo);
    cudaGetSymbolAddress((void**)&p_wqh, g_wqt_hi);
    cudaGetSymbolAddress((void**)&p_wql, g_wqt_lo);
    cudaGetSymbolAddress((void**)&p_wkh, g_wkt_hi);
    cudaGetSymbolAddress((void**)&p_wkl, g_wkt_lo);
    cudaGetSymbolAddress((void**)&p_wvh, g_wvt_hi);
    cudaGetSymbolAddress((void**)&p_wvl, g_wvt_lo);
    cudaGetSymbolAddress((void**)&p_wgh, g_wgt_hi);
    cudaGetSymbolAddress((void**)&p_wgl, g_wgt_lo);
    cudaGetSymbolAddress((void**)&p_woh, g_wot_hi);
    cudaGetSymbolAddress((void**)&p_wol, g_wot_lo);

    // 0) precision-split conversions
    hilo_kernel<<<(ROWS * DH_ / 2 + 255) / 256, 256>>>(x, p_xhi, p_xlo, ROWS * DH_ / 2);
    transpose_hilo<<<dim3(DH_ / 32, DH_ / 32), 256>>>(Wq, p_wqh, p_wql, DH_, DH_);
    transpose_hilo<<<dim3(512 / 32, DH_ / 32), 256>>>(Wk, p_wkh, p_wkl, DH_, 512);
    transpose_hilo<<<dim3(512 / 32, DH_ / 32), 256>>>(Wv, p_wvh, p_wvl, DH_, 512);
    transpose_hilo<<<dim3(DH_ / 32, DH_ / 32), 256>>>(Wg, p_wgh, p_wgl, DH_, DH_);
    transpose_hilo<<<dim3(DH_ / 32, DH_ / 32), 256>>>(Wo, p_woh, p_wol, DH_, DH_);

    // 1) projections (mma.sync bf16 hi/lo)
    gemm_mma<<<dim3(16, 32), 256, SM_GEMM>>>(p_xhi, p_xlo, p_wqh, p_wql, p_xq, 2048, DH_);
    gemm_mma<<<dim3( 4, 32), 256, SM_GEMM>>>(p_xhi, p_xlo, p_wkh, p_wkl, p_xk,  512, DH_);
    gemm_mma<<<dim3( 4, 32), 256, SM_GEMM>>>(p_xhi, p_xlo, p_wvh, p_wvl, p_xv,  512, DH_);
    gemm_mma<<<dim3(16, 32), 256, SM_GEMM>>>(p_xhi, p_xlo, p_wgh, p_wgl, p_xg, 2048, DH_);
    betag_kernel<<<ROWS, 256>>>(x, Wb, Wgk, A_log, dt_b);

    // 2) conv + silu (+ l2 norm; q scaled by D^-0.5)
    conv_kernel<<<dim3(ROWS, 16), 128>>>(p_xq, convq, p_q, 2048, 1, 0.08838834764831845f);
    conv_kernel<<<dim3(ROWS,  4), 128>>>(p_xk, convk, p_k,  512, 1, 1.f);
    conv_kernel<<<dim3(ROWS,  4), 128>>>(p_xv, convv, p_v,  512, 0, 1.f);

    // 3) recurrence
    recurrence_kernel<<<64, 128>>>();

    // 4) gated rmsnorm (-> bf16 hi/lo)
    rmsgate_kernel<<<dim3(ROWS, 16), 128>>>(p_xg, onw);

    // 5) output projection (mma.sync)
    gemm_mma<<<dim3(16, 32), 256, SM_GEMM>>>(p_ofhi, p_oflo, p_woh, p_wol, out, 2048, DH_);
}

// round 5
// speedup vs baseline: 2.4324x; 1.4478x over previous
#include <cuda_runtime.h>
#include <cuda_bf16.h>
#include <math.h>
#include <stdint.h>

// ---------------------------------------------------------------------------
// Problem constants: B=4, L=1024, DH=2048, D=128, HQ=16, HK=HV=4, H=16, K=4
// Fused projection layout (columns of xcat / rows of wcat):
//   [0,2048) q | [2048,2560) k | [2560,3072) v | [3072,5120) g
//   [5120,5136) beta-logit | [5136,5152) g-logit | [5152,5248) zero pad
// ---------------------------------------------------------------------------
#define ROWS 4096
#define DH_  2048
#define DHEAD 128
#define NH   16
#define NHK  4
#define SEQ  1024
#define NCAT 5248
#define COL_K 2048
#define COL_V 2560
#define COL_G 3072
#define COL_B 5120
#define COL_GK 5136

// ---------------- device scratch (allocation-free rule) --------------------
__device__ float g_xcat[ROWS * NCAT];     // fused projection output
__device__ float g_q [ROWS * DH_];
__device__ float g_k [ROWS * 512];
__device__ float g_v [ROWS * 512];
__device__ float g_beta[ROWS * NH];
__device__ float g_gd  [ROWS * NH];
__device__ float g_o [ROWS * DH_];

__device__ __align__(256) __nv_bfloat16 g_xhi[ROWS * DH_];
__device__ __align__(256) __nv_bfloat16 g_xlo[ROWS * DH_];
__device__ __align__(256) __nv_bfloat16 g_ofhi[ROWS * DH_];
__device__ __align__(256) __nv_bfloat16 g_oflo[ROWS * DH_];
__device__ __align__(256) __nv_bfloat16 g_wcat_hi[NCAT * DH_];   // [N=5248, K=2048]
__device__ __align__(256) __nv_bfloat16 g_wcat_lo[NCAT * DH_];
__device__ __align__(256) __nv_bfloat16 g_wot_hi[DH_ * DH_];
__device__ __align__(256) __nv_bfloat16 g_wot_lo[DH_ * DH_];

// ---------------------------------------------------------------------------
// PTX helpers (baseline ISA only)
// ---------------------------------------------------------------------------
__device__ __forceinline__ uint32_t smem_to_u32(const void* p) {
    uint32_t a;
    asm("{ .reg .u64 t; cvta.to.shared.u64 t, %1; cvt.u32.u64 %0, t; }"
        : "=r"(a) : "l"(p));
    return a;
}
__device__ __forceinline__ void cp16(uint32_t s, const void* g) {
    asm volatile("cp.async.cg.shared.global [%0], [%1], 16;"
                 :: "r"(s), "l"(g) : "memory");
}
#define CP_COMMIT() asm volatile("cp.async.commit_group;" ::: "memory")

#define LDSM4(d, addr) \
    asm volatile("ldmatrix.sync.aligned.m8n8.x4.shared.b16 {%0,%1,%2,%3}, [%4];" \
        : "=r"((d)[0]), "=r"((d)[1]), "=r"((d)[2]), "=r"((d)[3]) : "r"(addr))

#define MMA16816(c, a, b) \
    asm volatile("mma.sync.aligned.m16n8k16.row.col.f32.bf16.bf16.f32 " \
        "{%0,%1,%2,%3}, {%4,%5,%6,%7}, {%8,%9}, {%0,%1,%2,%3};" \
        : "+f"((c)[0]), "+f"((c)[1]), "+f"((c)[2]), "+f"((c)[3]) \
        : "r"((a)[0]), "r"((a)[1]), "r"((a)[2]), "r"((a)[3]), \
          "r"((b)[0]), "r"((b)[1]))

// ---------------------------------------------------------------------------
// fp32 -> bf16 hi/lo split
// ---------------------------------------------------------------------------
__global__ __launch_bounds__(256) void hilo_kernel(
    const float* __restrict__ in, __nv_bfloat16* __restrict__ hi,
    __nv_bfloat16* __restrict__ lo, int n2)
{
    int i = blockIdx.x * 256 + threadIdx.x;
    if (i >= n2) return;
    float2 v = ((const float2*)in)[i];
    __nv_bfloat16 h0 = __float2bfloat16_rn(v.x);
    __nv_bfloat16 h1 = __float2bfloat16_rn(v.y);
    __nv_bfloat16 l0 = __float2bfloat16_rn(v.x - __bfloat162float(h0));
    __nv_bfloat16 l1 = __float2bfloat16_rn(v.y - __bfloat162float(h1));
    ((__nv_bfloat162*)hi)[i] = __halves2bfloat162(h0, h1);
    ((__nv_bfloat162*)lo)[i] = __halves2bfloat162(l0, l1);
}

// ---------------------------------------------------------------------------
// W [K,N] fp32 -> Wt [N,K] bf16 hi/lo (tiled transpose)
// ---------------------------------------------------------------------------
__global__ __launch_bounds__(256) void transpose_hilo(
    const float* __restrict__ W, __nv_bfloat16* __restrict__ Thi,
    __nv_bfloat16* __restrict__ Tlo, int K, int N)
{
    __shared__ float t[32][33];
    const int bx = blockIdx.x * 32;   // N
    const int by = blockIdx.y * 32;   // K
    const int tx = threadIdx.x & 31, ty = threadIdx.x >> 5;
    #pragma unroll
    for (int i = 0; i < 32; i += 8)
        t[ty + i][tx] = W[(size_t)(by + ty + i) * N + bx + tx];
    __syncthreads();
    #pragma unroll
    for (int i = 0; i < 32; i += 8) {
        float v = t[tx][ty + i];
        __nv_bfloat16 h = __float2bfloat16_rn(v);
        size_t o = (size_t)(bx + ty + i) * K + by + tx;
        Thi[o] = h;
        Tlo[o] = __float2bfloat16_rn(v - __bfloat162float(h));
    }
}

// Wb, Wgk [2048,16] -> wcat rows [5120..5152) (pointer pre-offset to row 5120)
__global__ __launch_bounds__(256) void transpose_bg(
    const float* __restrict__ Wb, const float* __restrict__ Wgk,
    __nv_bfloat16* __restrict__ Thi, __nv_bfloat16* __restrict__ Tlo)
{
    int i = blockIdx.x * 256 + threadIdx.x;       // 0 .. 16*2048-1
    if (i >= 16 * DH_) return;
    int k = i >> 4, n = i & 15;
    float vb = Wb[(size_t)k * NH + n];
    float vg = Wgk[(size_t)k * NH + n];
    __nv_bfloat16 hb = __float2bfloat16_rn(vb);
    __nv_bfloat16 hg = __float2bfloat16_rn(vg);
    size_t ob = (size_t)n * DH_ + k;
    size_t og = (size_t)(16 + n) * DH_ + k;
    Thi[ob] = hb; Tlo[ob] = __float2bfloat16_rn(vb - __bfloat162float(hb));
    Thi[og] = hg; Tlo[og] = __float2bfloat16_rn(vg - __bfloat162float(hg));
}

// ---------------------------------------------------------------------------
// bf16 mma.sync GEMM with hi/lo compensation (hh + hl + lh):
//   C[M,N] = (Ahi+Alo)[M,K] @ (Bhi+Blo)[N,K]^T, fp32 accumulate
// BM=BN=128, BK=32 (64B rows), 3 stages (96KB), 256 thr, 2 CTAs/SM.
// ---------------------------------------------------------------------------
#define ST_BYTES 32768          // Ahi 8K | Alo 8K | Bhi 8K | Blo 8K
#define SM_GEMM  (3 * ST_BYTES)

__global__ __launch_bounds__(256, 2) void gemm_mma(
    const __nv_bfloat16* __restrict__ Ahi, const __nv_bfloat16* __restrict__ Alo,
    const __nv_bfloat16* __restrict__ Bhi, const __nv_bfloat16* __restrict__ Blo,
    float* __restrict__ C, int N, int K)
{
    extern __shared__ char smem[];
    const uint32_t sb = smem_to_u32(smem);
    const int tid  = threadIdx.x;
    const int lane = tid & 31;
    const int wid  = tid >> 5;
    const int wm   = wid & 1;        // 0..1
    const int wn   = wid >> 1;       // 0..3
    const int brow = blockIdx.y * 128;
    const int bcol = blockIdx.x * 128;
    const size_t K2 = (size_t)K * 2;   // bytes per row

    // per-thread cp.async descriptors: 2 x 16B per 8KB buffer
    uint32_t swo[2];
    size_t   ga[2], gb[2];
    #pragma unroll
    for (int i = 0; i < 2; i++) {
        int c  = tid + (i << 8);       // 0..511
        int r  = c >> 2;               // row 0..127
        int ch = c & 3;                // 16B chunk 0..3
        swo[i] = (uint32_t)(r * 64 + ((ch ^ ((r >> 1) & 3)) << 4));
        ga[i]  = (size_t)(brow + r) * K2 + (size_t)(ch << 4);
        gb[i]  = (size_t)(bcol + r) * K2 + (size_t)(ch << 4);
    }

    const int NK = K >> 5;   // BK=32

    // prologue: stages 0,1
    #pragma unroll
    for (int pf = 0; pf < 2; pf++) {
        uint32_t s0 = sb + pf * ST_BYTES;
        size_t ko = (size_t)pf << 6;   // kt*64 bytes
        #pragma unroll
        for (int i = 0; i < 2; i++) {
            cp16(s0 +     0 + swo[i], (const char*)Ahi + ga[i] + ko);
            cp16(s0 +  8192 + swo[i], (const char*)Alo + ga[i] + ko);
            cp16(s0 + 16384 + swo[i], (const char*)Bhi + gb[i] + ko);
            cp16(s0 + 24576 + swo[i], (const char*)Blo + gb[i] + ko);
        }
        CP_COMMIT();
    }

    float acc[4][4][4];
    #pragma unroll
    for (int mi = 0; mi < 4; mi++)
        #pragma unroll
        for (int ni = 0; ni < 4; ni++)
            #pragma unroll
            for (int j = 0; j < 4; j++) acc[mi][ni][j] = 0.f;

    int st_load = 2, st_cmp = 0;
    for (int kt = 0; kt < NK; kt++) {
        if (kt + 2 < NK) {
            uint32_t s0 = sb + st_load * ST_BYTES;
            size_t ko = (size_t)(kt + 2) << 6;
            #pragma unroll
            for (int i = 0; i < 2; i++) {
                cp16(s0 +     0 + swo[i], (const char*)Ahi + ga[i] + ko);
                cp16(s0 +  8192 + swo[i], (const char*)Alo + ga[i] + ko);
                cp16(s0 + 16384 + swo[i], (const char*)Bhi + gb[i] + ko);
                cp16(s0 + 24576 + swo[i], (const char*)Blo + gb[i] + ko);
            }
            CP_COMMIT();
            if (++st_load == 3) st_load = 0;
        }
        int ahead = NK - 1 - kt; if (ahead > 2) ahead = 2;
        if (ahead == 2)      asm volatile("cp.async.wait_group 2;" ::: "memory");
        else if (ahead == 1) asm volatile("cp.async.wait_group 1;" ::: "memory");
        else                 asm volatile("cp.async.wait_group 0;" ::: "memory");
        __syncthreads();

        const uint32_t sa = sb + st_cmp * ST_BYTES;
        #pragma unroll
        for (int ks = 0; ks < 2; ks++) {
            uint32_t ah[4][4], al[4][4];
            const int chA = (ks << 1) + (lane >> 4);
            #pragma unroll
            for (int mi = 0; mi < 4; mi++) {
                int r = wm * 64 + mi * 16 + (lane & 15);
                uint32_t ad = sa + (uint32_t)(r * 64 + ((chA ^ ((r >> 1) & 3)) << 4));
                LDSM4(ah[mi], ad);
                LDSM4(al[mi], ad + 8192);
            }
            uint32_t bh[4][2], bl[4][2];
            #pragma unroll
            for (int nb = 0; nb < 2; nb++) {
                int r = wn * 32 + nb * 16 + (lane & 15);
                uint32_t bd = sa + 16384u + (uint32_t)(r * 64 + ((chA ^ ((r >> 1) & 3)) << 4));
                uint32_t d[4];
                LDSM4(d, bd);
                bh[2*nb][0] = d[0]; bh[2*nb][1] = d[2];
                bh[2*nb+1][0] = d[1]; bh[2*nb+1][1] = d[3];
                LDSM4(d, bd + 8192);
                bl[2*nb][0] = d[0]; bl[2*nb][1] = d[2];
                bl[2*nb+1][0] = d[1]; bl[2*nb+1][1] = d[3];
            }
            #pragma unroll
            for (int mi = 0; mi < 4; mi++)
                #pragma unroll
                for (int ni = 0; ni < 4; ni++) {
                    MMA16816(acc[mi][ni], ah[mi], bh[ni]);
                    MMA16816(acc[mi][ni], ah[mi], bl[ni]);
                    MMA16816(acc[mi][ni], al[mi], bh[ni]);
                }
        }
        __syncthreads();
        if (++st_cmp == 3) st_cmp = 0;
    }

    #pragma unroll
    for (int mi = 0; mi < 4; mi++) {
        int r0 = brow + wm * 64 + mi * 16 + (lane >> 2);
        #pragma unroll
        for (int ni = 0; ni < 4; ni++) {
            int c0 = bcol + wn * 32 + ni * 8 + ((lane & 3) << 1);
            *(float2*)&C[(size_t)r0 * N + c0] =
                make_float2(acc[mi][ni][0], acc[mi][ni][1]);
            *(float2*)&C[(size_t)(r0 + 8) * N + c0] =
                make_float2(acc[mi][ni][2], acc[mi][ni][3]);
        }
    }
}

// ---------------------------------------------------------------------------
// beta/g from fused-GEMM logit columns
// ---------------------------------------------------------------------------
__global__ __launch_bounds__(256) void betag2_kernel(
    const float* __restrict__ xcat, const float* __restrict__ A_log,
    const float* __restrict__ dt_bias)
{
    int i = blockIdx.x * 256 + threadIdx.x;       // 0 .. ROWS*NH-1
    if (i >= ROWS * NH) return;
    int row = i >> 4, h = i & 15;
    float sbv = xcat[(size_t)row * NCAT + COL_B  + h];
    float sgv = xcat[(size_t)row * NCAT + COL_GK + h];
    g_beta[i] = 1.f / (1.f + expf(-sbv));
    float xg = sgv + dt_bias[h];
    float sp = (xg > 15.f) ? xg : log1pf(expf(xg));
    g_gd[i] = -expf(A_log[h]) * sp;
}

// ---------------------------------------------------------------------------
// Causal depthwise conv (K=4) + SiLU (+ optional L2 norm * scale)
// in: pre-offset into xcat, row stride NCAT. out: dense [rows, chans].
// ---------------------------------------------------------------------------
__global__ __launch_bounds__(128) void conv_kernel(
    const float* __restrict__ in, const float* __restrict__ w,
    float* __restrict__ out, int chans, int do_l2, float scale)
{
    const int row = blockIdx.x;
    const int c   = blockIdx.y * DHEAD + threadIdx.x;
    const int l   = row & (SEQ - 1);

    float acc = 0.f;
    #pragma unroll
    for (int j = 0; j < 4; j++) {
        int sl = l + j - 3;
        if (sl >= 0) acc += in[(size_t)(row + j - 3) * NCAT + c] * w[c * 4 + j];
    }
    float y = acc / (1.f + expf(-acc));

    if (do_l2) {
        __shared__ float sm[4];
        float ss = y * y;
        #pragma unroll
        for (int off = 16; off > 0; off >>= 1)
            ss += __shfl_xor_sync(0xffffffffu, ss, off);
        if ((threadIdx.x & 31) == 0) sm[threadIdx.x >> 5] = ss;
        __syncthreads();
        float tot = sm[0] + sm[1] + sm[2] + sm[3];
        y *= rsqrtf(tot + 1e-6f) * scale;
    }
    out[(size_t)row * chans + c] = y;
}

// ---------------------------------------------------------------------------
// Gated delta-rule recurrence, f32x2-packed, 128 CTAs.
// CTA = (b, h, column-half). Thread t: column col = half*64 + (t>>1),
// key block kb = t&1 (keys [kb*64, kb*64+64)). Partner reduce via shfl_xor(1).
// ---------------------------------------------------------------------------
#define FMA2(d, a, b, c) \
    asm("fma.rn.f32x2 %0, %1, %2, %3;" : "=l"(d) : "l"(a), "l"(b), "l"(c))
#define MUL2(d, a, b) \
    asm("mul.rn.f32x2 %0, %1, %2;" : "=l"(d) : "l"(a), "l"(b))

__device__ __forceinline__ unsigned long long f2pack(float a, float b) {
    unsigned long long r;
    asm("mov.b64 %0, {%1, %2};" : "=l"(r)
        : "r"(__float_as_uint(a)), "r"(__float_as_uint(b)));
    return r;
}
__device__ __forceinline__ float f2sum(unsigned long long v) {
    uint32_t x, y;
    asm("mov.b64 {%0, %1}, %2;" : "=r"(x), "=r"(y) : "l"(v));
    return __uint_as_float(x) + __uint_as_float(y);
}

__global__ __launch_bounds__(128) void recurrence_kernel()
{
    // padded: keys [0,64) at [0,64), keys [64,128) at [68,132)
    __shared__ __align__(16) float ks[2][136];
    __shared__ __align__(16) float qs[2][136];

    const int bx   = blockIdx.x;        // 0..127
    const int pair = bx >> 1;
    const int half = bx & 1;
    const int b  = pair >> 4;
    const int h  = pair & 15;
    const int kh = h >> 2;
    const int t  = threadIdx.x;
    const int col = half * 64 + (t >> 1);
    const int kb  = t & 1;
    const int wpos = (t < 64) ? t : t + 4;

    unsigned long long S2[32];          // 64 keys for one column
    #pragma unroll
    for (int d = 0; d < 32; d++) S2[d] = 0ull;

    const float* qp = g_q    + ((size_t)(b * SEQ) * NH  + h ) * DHEAD + t;
    const float* kp = g_k    + ((size_t)(b * SEQ) * NHK + kh) * DHEAD + t;
    const float* vp = g_v    + ((size_t)(b * SEQ) * NHK + kh) * DHEAD + col;
    const float* gp = g_gd   +  (size_t)(b * SEQ) * NH + h;
    const float* bp = g_beta +  (size_t)(b * SEQ) * NH + h;
    float*       op = g_o    + ((size_t)(b * SEQ) * NH  + h ) * DHEAD + col;

    float kcur = kp[0], qcur = qp[0];
    float vcur = vp[0], gcur = gp[0], bcur = bp[0];
    ks[0][wpos] = kcur; qs[0][wpos] = qcur;
    __syncthreads();

    for (int l = 0; l < SEQ; l++) {
        const int cur = l & 1, nxt = cur ^ 1;
        float knx = 0.f, qnx = 0.f, vnx = 0.f, gnx = 0.f, bnx = 0.f;
        if (l + 1 < SEQ) {
            knx = kp[(size_t)(l + 1) * 512];
            qnx = qp[(size_t)(l + 1) * 2048];
            vnx = vp[(size_t)(l + 1) * 512];
            gnx = gp[(size_t)(l + 1) * NH];
            bnx = bp[(size_t)(l + 1) * NH];
        }

        const float eg = expf(gcur);
        const unsigned long long eg2 = f2pack(eg, eg);
        const ulonglong2* k2p = reinterpret_cast<const ulonglong2*>(&ks[cur][kb * 68]);
        const ulonglong2* q2p = reinterpret_cast<const ulonglong2*>(&qs[cur][kb * 68]);

        unsigned long long kva = 0ull, kvb = 0ull;
        #pragma unroll
        for (int i = 0; i < 16; i++) {
            ulonglong2 kk = k2p[i];
            MUL2(S2[2 * i], S2[2 * i], eg2);
            FMA2(kva, kk.x, S2[2 * i], kva);
            MUL2(S2[2 * i + 1], S2[2 * i + 1], eg2);
            FMA2(kvb, kk.y, S2[2 * i + 1], kvb);
        }
        float kvp = f2sum(kva) + f2sum(kvb);
        kvp += __shfl_xor_sync(0xffffffffu, kvp, 1);
        const float cc = bcur * (vcur - kvp);
        const unsigned long long cc2 = f2pack(cc, cc);

        unsigned long long qa = 0ull, qb = 0ull;
        #pragma unroll
        for (int i = 0; i < 16; i++) {
            ulonglong2 kk = k2p[i];
            ulonglong2 qq = q2p[i];
            FMA2(S2[2 * i], kk.x, cc2, S2[2 * i]);
            FMA2(qa, qq.x, S2[2 * i], qa);
            FMA2(S2[2 * i + 1], kk.y, cc2, S2[2 * i + 1]);
            FMA2(qb, qq.y, S2[2 * i + 1], qb);
        }
        float qo = f2sum(qa) + f2sum(qb);
        qo += __shfl_xor_sync(0xffffffffu, qo, 1);
        if (kb == 0) op[(size_t)l * 2048] = qo;

        ks[nxt][wpos] = knx; qs[nxt][wpos] = qnx;
        __syncthreads();
        vcur = vnx; gcur = gnx; bcur = bnx;
    }
}

// ---------------------------------------------------------------------------
// FusedRMSNormGated -> bf16 hi/lo (gate from xcat col 3072+)
// ---------------------------------------------------------------------------
__global__ __launch_bounds__(128) void rmsgate_kernel(
    const float* __restrict__ xcat, const float* __restrict__ w)
{
    const int row = blockIdx.x;
    const int h   = blockIdx.y;
    const int t   = threadIdx.x;

    const size_t idx = (size_t)(row * NH + h) * DHEAD + t;
    float o = g_o[idx];

    float ss = o * o;
    #pragma unroll
    for (int off = 16; off > 0; off >>= 1)
        ss += __shfl_xor_sync(0xffffffffu, ss, off);
    __shared__ float sm[4];
    if ((t & 31) == 0) sm[t >> 5] = ss;
    __syncthreads();
    float tot = sm[0] + sm[1] + sm[2] + sm[3];
    float r = rsqrtf(tot * (1.f / 128.f) + 1e-5f);

    float gate = xcat[(size_t)row * NCAT + COL_G + h * DHEAD + t];
    float sg   = gate / (1.f + expf(-gate));
    float val  = o * r * w[t] * sg;

    size_t oo = (size_t)row * DH_ + h * DHEAD + t;
    __nv_bfloat16 hi = __float2bfloat16_rn(val);
    g_ofhi[oo] = hi;
    g_oflo[oo] = __float2bfloat16_rn(val - __bfloat162float(hi));
}

// ---------------------------------------------------------------------------
// Launch
// ---------------------------------------------------------------------------
extern "C" void kernel_launch(void* const* d_in, const int* in_sizes, int n_in,
                              void* d_out, int out_size)
{
    (void)in_sizes; (void)n_in; (void)out_size;
    const float* x     = (const float*)d_in[0];
    const float* Wq    = (const float*)d_in[1];
    const float* Wk    = (const float*)d_in[2];
    const float* Wv    = (const float*)d_in[3];
    const float* Wb    = (const float*)d_in[4];
    const float* Wgk   = (const float*)d_in[5];
    const float* A_log = (const float*)d_in[6];
    const float* dt_b  = (const float*)d_in[7];
    const float* convq = (const float*)d_in[8];
    const float* convk = (const float*)d_in[9];
    const float* convv = (const float*)d_in[10];
    const float* Wg    = (const float*)d_in[11];
    const float* onw   = (const float*)d_in[12];
    const float* Wo    = (const float*)d_in[13];
    float* out = (float*)d_out;

    cudaFuncSetAttribute(gemm_mma, cudaFuncAttributeMaxDynamicSharedMemorySize, SM_GEMM);

    float *p_xcat, *p_q, *p_k, *p_v;
    __nv_bfloat16 *p_xhi, *p_xlo, *p_ofhi, *p_oflo;
    __nv_bfloat16 *p_wch, *p_wcl, *p_woh, *p_wol;
    cudaGetSymbolAddress((void**)&p_xcat, g_xcat);
    cudaGetSymbolAddress((void**)&p_q,  g_q);
    cudaGetSymbolAddress((void**)&p_k,  g_k);
    cudaGetSymbolAddress((void**)&p_v,  g_v);
    cudaGetSymbolAddress((void**)&p_xhi, g_xhi);
    cudaGetSymbolAddress((void**)&p_xlo, g_xlo);
    cudaGetSymbolAddress((void**)&p_ofhi, g_ofhi);
    cudaGetSymbolAddress((void**)&p_oflo, g_oflo);
    cudaGetSymbolAddress((void**)&p_wch, g_wcat_hi);
    cudaGetSymbolAddress((void**)&p_wcl, g_wcat_lo);
    cudaGetSymbolAddress((void**)&p_woh, g_wot_hi);
    cudaGetSymbolAddress((void**)&p_wol, g_wot_lo);

    // 0) precision-split conversions into the fused weight matrix
    hilo_kernel<<<(ROWS * DH_ / 2 + 255) / 256, 256>>>(x, p_xhi, p_xlo, ROWS * DH_ / 2);
    transpose_hilo<<<dim3(DH_/32, DH_/32), 256>>>(Wq, p_wch,                        p_wcl,                        DH_, DH_);
    transpose_hilo<<<dim3(512/32, DH_/32), 256>>>(Wk, p_wch + (size_t)COL_K * DH_,  p_wcl + (size_t)COL_K * DH_,  DH_, 512);
    transpose_hilo<<<dim3(512/32, DH_/32), 256>>>(Wv, p_wch + (size_t)COL_V * DH_,  p_wcl + (size_t)COL_V * DH_,  DH_, 512);
    transpose_hilo<<<dim3(DH_/32, DH_/32), 256>>>(Wg, p_wch + (size_t)COL_G * DH_,  p_wcl + (size_t)COL_G * DH_,  DH_, DH_);
    transpose_bg<<<(16 * DH_ + 255) / 256, 256>>>(Wb, Wgk, p_wch + (size_t)COL_B * DH_, p_wcl + (size_t)COL_B * DH_);
    transpose_hilo<<<dim3(DH_/32, DH_/32), 256>>>(Wo, p_woh, p_wol, DH_, DH_);

    // 1) fused projection GEMM: xcat[4096, 5248]
    gemm_mma<<<dim3(NCAT / 128, 32), 256, SM_GEMM>>>(p_xhi, p_xlo, p_wch, p_wcl, p_xcat, NCAT, DH_);
    betag2_kernel<<<(ROWS * NH + 255) / 256, 256>>>(p_xcat, A_log, dt_b);

    // 2) conv + silu (+ l2 norm; q scaled by D^-0.5)
    conv_kernel<<<dim3(ROWS, 16), 128>>>(p_xcat,         convq, p_q, 2048, 1, 0.08838834764831845f);
    conv_kernel<<<dim3(ROWS,  4), 128>>>(p_xcat + COL_K, convk, p_k,  512, 1, 1.f);
    conv_kernel<<<dim3(ROWS,  4), 128>>>(p_xcat + COL_V, convv, p_v,  512, 0, 1.f);

    // 3) recurrence (128 CTAs)
    recurrence_kernel<<<128, 128>>>();

    // 4) gated rmsnorm (-> bf16 hi/lo)
    rmsgate_kernel<<<dim3(ROWS, 16), 128>>>(p_xcat, onw);

    // 5) output projection
    gemm_mma<<<dim3(16, 32), 256, SM_GEMM>>>(p_ofhi, p_oflo, p_woh, p_wol, out, 2048, DH_);
}

// round 6
// speedup vs baseline: 2.6098x; 1.0729x over previous
#include <cuda_runtime.h>
#include <cuda_fp16.h>
#include <math.h>
#include <stdint.h>

// ---------------------------------------------------------------------------
// Problem constants: B=4, L=1024, DH=2048, D=128, HQ=16, HK=HV=4, H=16, K=4
// Fused projection layout (columns of xcat / rows of wcat):
//   [0,2048) q | [2048,2560) k | [2560,3072) v | [3072,5120) g
// ---------------------------------------------------------------------------
#define ROWS 4096
#define DH_  2048
#define DHEAD 128
#define NH   16
#define NHK  4
#define SEQ  1024
#define NCAT 5120
#define COL_K 2048
#define COL_V 2560
#define COL_G 3072

// ---------------- device scratch (allocation-free rule) --------------------
__device__ float g_xcat[ROWS * NCAT];     // fused projection output
__device__ float g_q [ROWS * DH_];
__device__ float g_k [ROWS * 512];
__device__ float g_v [ROWS * 512];
__device__ float g_beta[ROWS * NH];
__device__ float g_gd  [ROWS * NH];
__device__ float g_o [ROWS * DH_];

__device__ __align__(256) __half g_xhi[ROWS * DH_];
__device__ __align__(256) __half g_xlo[ROWS * DH_];
__device__ __align__(256) __half g_ofhi[ROWS * DH_];
__device__ __align__(256) __half g_oflo[ROWS * DH_];
__device__ __align__(256) __half g_wcat[NCAT * DH_];     // [N=5120, K=2048] fp16
__device__ __align__(256) __half g_wot[DH_ * DH_];       // Wo^T fp16

// ---------------------------------------------------------------------------
// PTX helpers (baseline ISA only)
// ---------------------------------------------------------------------------
__device__ __forceinline__ uint32_t smem_to_u32(const void* p) {
    uint32_t a;
    asm("{ .reg .u64 t; cvta.to.shared.u64 t, %1; cvt.u32.u64 %0, t; }"
        : "=r"(a) : "l"(p));
    return a;
}
__device__ __forceinline__ void cp16(uint32_t s, const void* g) {
    asm volatile("cp.async.cg.shared.global [%0], [%1], 16;"
                 :: "r"(s), "l"(g) : "memory");
}
#define CP_COMMIT() asm volatile("cp.async.commit_group;" ::: "memory")

#define LDSM4(d, addr) \
    asm volatile("ldmatrix.sync.aligned.m8n8.x4.shared.b16 {%0,%1,%2,%3}, [%4];" \
        : "=r"((d)[0]), "=r"((d)[1]), "=r"((d)[2]), "=r"((d)[3]) : "r"(addr))

#define MMA16816F(c, a, b) \
    asm volatile("mma.sync.aligned.m16n8k16.row.col.f32.f16.f16.f32 " \
        "{%0,%1,%2,%3}, {%4,%5,%6,%7}, {%8,%9}, {%0,%1,%2,%3};" \
        : "+f"((c)[0]), "+f"((c)[1]), "+f"((c)[2]), "+f"((c)[3]) \
        : "r"((a)[0]), "r"((a)[1]), "r"((a)[2]), "r"((a)[3]), \
          "r"((b)[0]), "r"((b)[1]))

// ---------------------------------------------------------------------------
// fp32 -> fp16 hi/lo split (A side stays exact across the 2-pass GEMM)
// ---------------------------------------------------------------------------
__global__ __launch_bounds__(256) void hilo_kernel(
    const float* __restrict__ in, __half* __restrict__ hi,
    __half* __restrict__ lo, int n2)
{
    int i = blockIdx.x * 256 + threadIdx.x;
    if (i >= n2) return;
    float2 v = ((const float2*)in)[i];
    __half h0 = __float2half_rn(v.x);
    __half h1 = __float2half_rn(v.y);
    __half l0 = __float2half_rn(v.x - __half2float(h0));
    __half l1 = __float2half_rn(v.y - __half2float(h1));
    ((__half2*)hi)[i] = __halves2half2(h0, h1);
    ((__half2*)lo)[i] = __halves2half2(l0, l1);
}

// ---------------------------------------------------------------------------
// W [K,N] fp32 -> Wt [N,K] fp16 (tiled transpose, single rounding)
// ---------------------------------------------------------------------------
__global__ __launch_bounds__(256) void transpose_f16(
    const float* __restrict__ W, __half* __restrict__ T, int K, int N)
{
    __shared__ float t[32][33];
    const int bx = blockIdx.x * 32;   // N
    const int by = blockIdx.y * 32;   // K
    const int tx = threadIdx.x & 31, ty = threadIdx.x >> 5;
    #pragma unroll
    for (int i = 0; i < 32; i += 8)
        t[ty + i][tx] = W[(size_t)(by + ty + i) * N + bx + tx];
    __syncthreads();
    #pragma unroll
    for (int i = 0; i < 32; i += 8)
        T[(size_t)(bx + ty + i) * K + by + tx] = __float2half_rn(t[tx][ty + i]);
}

// ---------------------------------------------------------------------------
// fp16 mma.sync GEMM, 2-pass A-split:  C = (Ahi + Alo)[M,K] @ B[N,K]^T
// BM=BN=128, BK=32 (64B rows), 4 stages (96KB), 256 thr, 2 CTAs/SM.
// ---------------------------------------------------------------------------
#define ST_BYTES 24576          // Ahi 8K | Alo 8K | B 8K
#define SM_GEMM  (4 * ST_BYTES)

__global__ __launch_bounds__(256, 2) void gemm_mma(
    const __half* __restrict__ Ahi, const __half* __restrict__ Alo,
    const __half* __restrict__ B,
    float* __restrict__ C, int N, int K)
{
    extern __shared__ char smem[];
    const uint32_t sb = smem_to_u32(smem);
    const int tid  = threadIdx.x;
    const int lane = tid & 31;
    const int wid  = tid >> 5;
    const int wm   = wid & 1;        // 0..1
    const int wn   = wid >> 1;       // 0..3
    const int brow = blockIdx.y * 128;
    const int bcol = blockIdx.x * 128;
    const size_t K2 = (size_t)K * 2;   // bytes per row

    // per-thread cp.async descriptors: 2 x 16B per 8KB buffer
    uint32_t swo[2];
    size_t   ga[2], gb[2];
    #pragma unroll
    for (int i = 0; i < 2; i++) {
        int c  = tid + (i << 8);       // 0..511
        int r  = c >> 2;               // row 0..127
        int ch = c & 3;                // 16B chunk 0..3
        swo[i] = (uint32_t)(r * 64 + ((ch ^ ((r >> 1) & 3)) << 4));
        ga[i]  = (size_t)(brow + r) * K2 + (size_t)(ch << 4);
        gb[i]  = (size_t)(bcol + r) * K2 + (size_t)(ch << 4);
    }

    const int NK = K >> 5;   // BK=32

    // prologue: stages 0..2
    #pragma unroll
    for (int pf = 0; pf < 3; pf++) {
        uint32_t s0 = sb + pf * ST_BYTES;
        size_t ko = (size_t)pf << 6;   // kt*64 bytes
        #pragma unroll
        for (int i = 0; i < 2; i++) {
            cp16(s0 +     0 + swo[i], (const char*)Ahi + ga[i] + ko);
            cp16(s0 +  8192 + swo[i], (const char*)Alo + ga[i] + ko);
            cp16(s0 + 16384 + swo[i], (const char*)B   + gb[i] + ko);
        }
        CP_COMMIT();
    }

    float acc[4][4][4];
    #pragma unroll
    for (int mi = 0; mi < 4; mi++)
        #pragma unroll
        for (int ni = 0; ni < 4; ni++)
            #pragma unroll
            for (int j = 0; j < 4; j++) acc[mi][ni][j] = 0.f;

    int st_load = 3, st_cmp = 0;
    for (int kt = 0; kt < NK; kt++) {
        if (kt + 3 < NK) {
            uint32_t s0 = sb + st_load * ST_BYTES;
            size_t ko = (size_t)(kt + 3) << 6;
            #pragma unroll
            for (int i = 0; i < 2; i++) {
                cp16(s0 +     0 + swo[i], (const char*)Ahi + ga[i] + ko);
                cp16(s0 +  8192 + swo[i], (const char*)Alo + ga[i] + ko);
                cp16(s0 + 16384 + swo[i], (const char*)B   + gb[i] + ko);
            }
            CP_COMMIT();
            if (++st_load == 4) st_load = 0;
        }
        int ahead = NK - 1 - kt; if (ahead > 3) ahead = 3;
        if (ahead == 3)      asm volatile("cp.async.wait_group 3;" ::: "memory");
        else if (ahead == 2) asm volatile("cp.async.wait_group 2;" ::: "memory");
        else if (ahead == 1) asm volatile("cp.async.wait_group 1;" ::: "memory");
        else                 asm volatile("cp.async.wait_group 0;" ::: "memory");
        __syncthreads();

        const uint32_t sa = sb + st_cmp * ST_BYTES;
        #pragma unroll
        for (int ks = 0; ks < 2; ks++) {
            uint32_t ah[4][4], al[4][4];
            const int chA = (ks << 1) + (lane >> 4);
            #pragma unroll
            for (int mi = 0; mi < 4; mi++) {
                int r = wm * 64 + mi * 16 + (lane & 15);
                uint32_t ad = sa + (uint32_t)(r * 64 + ((chA ^ ((r >> 1) & 3)) << 4));
                LDSM4(ah[mi], ad);
                LDSM4(al[mi], ad + 8192);
            }
            uint32_t bh[4][2];
            #pragma unroll
            for (int nb = 0; nb < 2; nb++) {
                int r = wn * 32 + nb * 16 + (lane & 15);
                uint32_t bd = sa + 16384u + (uint32_t)(r * 64 + ((chA ^ ((r >> 1) & 3)) << 4));
                uint32_t d[4];
                LDSM4(d, bd);
                bh[2*nb][0] = d[0]; bh[2*nb][1] = d[2];
                bh[2*nb+1][0] = d[1]; bh[2*nb+1][1] = d[3];
            }
            #pragma unroll
            for (int mi = 0; mi < 4; mi++)
                #pragma unroll
                for (int ni = 0; ni < 4; ni++) {
                    MMA16816F(acc[mi][ni], ah[mi], bh[ni]);
                    MMA16816F(acc[mi][ni], al[mi], bh[ni]);
                }
        }
        __syncthreads();
        if (++st_cmp == 4) st_cmp = 0;
    }

    #pragma unroll
    for (int mi = 0; mi < 4; mi++) {
        int r0 = brow + wm * 64 + mi * 16 + (lane >> 2);
        #pragma unroll
        for (int ni = 0; ni < 4; ni++) {
            int c0 = bcol + wn * 32 + ni * 8 + ((lane & 3) << 1);
            *(float2*)&C[(size_t)r0 * N + c0] =
                make_float2(acc[mi][ni][0], acc[mi][ni][1]);
            *(float2*)&C[(size_t)(r0 + 8) * N + c0] =
                make_float2(acc[mi][ni][2], acc[mi][ni][3]);
        }
    }
}

// ---------------------------------------------------------------------------
// Exact fp32 beta/g: beta = sigmoid(x@Wb), g = -exp(A_log)*softplus(x@Wgk+dt)
// (kept in fp32 because decay-logit errors amplify over the 1024-step scan)
// ---------------------------------------------------------------------------
__global__ __launch_bounds__(256) void betag_kernel(
    const float* __restrict__ x, const float* __restrict__ Wb,
    const float* __restrict__ Wgk, const float* __restrict__ A_log,
    const float* __restrict__ dt_bias)
{
    __shared__ float xs[DH_];
    const int row = blockIdx.x;
    for (int i = threadIdx.x; i < DH_; i += 256) xs[i] = x[(size_t)row * DH_ + i];
    __syncthreads();

    const int o     = threadIdx.x >> 3;
    const int lane8 = threadIdx.x & 7;
    const int h     = o & 15;
    const float* W  = (o < 16) ? Wb : Wgk;

    float s = 0.f;
    for (int c = lane8; c < DH_; c += 8) s += xs[c] * W[c * NH + h];
    #pragma unroll
    for (int off = 4; off > 0; off >>= 1)
        s += __shfl_down_sync(0xffffffffu, s, off, 8);

    if (lane8 == 0) {
        if (o < 16) {
            g_beta[row * NH + h] = 1.f / (1.f + expf(-s));
        } else {
            float xg = s + dt_bias[h];
            float sp = (xg > 15.f) ? xg : log1pf(expf(xg));
            g_gd[row * NH + h] = -expf(A_log[h]) * sp;
        }
    }
}

// ---------------------------------------------------------------------------
// Causal depthwise conv (K=4) + SiLU (+ optional L2 norm * scale)
// in: pre-offset into xcat, row stride NCAT. out: dense [rows, chans].
// ---------------------------------------------------------------------------
__global__ __launch_bounds__(128) void conv_kernel(
    const float* __restrict__ in, const float* __restrict__ w,
    float* __restrict__ out, int chans, int do_l2, float scale)
{
    const int row = blockIdx.x;
    const int c   = blockIdx.y * DHEAD + threadIdx.x;
    const int l   = row & (SEQ - 1);

    float acc = 0.f;
    #pragma unroll
    for (int j = 0; j < 4; j++) {
        int sl = l + j - 3;
        if (sl >= 0) acc += in[(size_t)(row + j - 3) * NCAT + c] * w[c * 4 + j];
    }
    float y = acc / (1.f + expf(-acc));

    if (do_l2) {
        __shared__ float sm[4];
        float ss = y * y;
        #pragma unroll
        for (int off = 16; off > 0; off >>= 1)
            ss += __shfl_xor_sync(0xffffffffu, ss, off);
        if ((threadIdx.x & 31) == 0) sm[threadIdx.x >> 5] = ss;
        __syncthreads();
        float tot = sm[0] + sm[1] + sm[2] + sm[3];
        y *= rsqrtf(tot + 1e-6f) * scale;
    }
    out[(size_t)row * chans + c] = y;
}

// ---------------------------------------------------------------------------
// Gated delta-rule recurrence, f32x2-packed, 128 CTAs.
// CTA = (b, h, column-half). Thread t: column col = half*64 + (t>>1),
// key block kb = t&1 (keys [kb*64, kb*64+64)). Partner reduce via shfl_xor(1).
// ---------------------------------------------------------------------------
#define FMA2(d, a, b, c) \
    asm("fma.rn.f32x2 %0, %1, %2, %3;" : "=l"(d) : "l"(a), "l"(b), "l"(c))
#define MUL2(d, a, b) \
    asm("mul.rn.f32x2 %0, %1, %2;" : "=l"(d) : "l"(a), "l"(b))

__device__ __forceinline__ unsigned long long f2pack(float a, float b) {
    unsigned long long r;
    asm("mov.b64 %0, {%1, %2};" : "=l"(r)
        : "r"(__float_as_uint(a)), "r"(__float_as_uint(b)));
    return r;
}
__device__ __forceinline__ float f2sum(unsigned long long v) {
    uint32_t x, y;
    asm("mov.b64 {%0, %1}, %2;" : "=r"(x), "=r"(y) : "l"(v));
    return __uint_as_float(x) + __uint_as_float(y);
}

__global__ __launch_bounds__(128) void recurrence_kernel()
{
    // padded: keys [0,64) at [0,64), keys [64,128) at [68,132)
    __shared__ __align__(16) float ks[2][136];
    __shared__ __align__(16) float qs[2][136];

    const int bx   = blockIdx.x;        // 0..127
    const int pair = bx >> 1;
    const int half = bx & 1;
    const int b  = pair >> 4;
    const int h  = pair & 15;
    const int kh = h >> 2;
    const int t  = threadIdx.x;
    const int col = half * 64 + (t >> 1);
    const int kb  = t & 1;
    const int wpos = (t < 64) ? t : t + 4;

    unsigned long long S2[32];          // 64 keys for one column
    #pragma unroll
    for (int d = 0; d < 32; d++) S2[d] = 0ull;

    const float* qp = g_q    + ((size_t)(b * SEQ) * NH  + h ) * DHEAD + t;
    const float* kp = g_k    + ((size_t)(b * SEQ) * NHK + kh) * DHEAD + t;
    const float* vp = g_v    + ((size_t)(b * SEQ) * NHK + kh) * DHEAD + col;
    const float* gp = g_gd   +  (size_t)(b * SEQ) * NH + h;
    const float* bp = g_beta +  (size_t)(b * SEQ) * NH + h;
    float*       op = g_o    + ((size_t)(b * SEQ) * NH  + h ) * DHEAD + col;

    float kcur = kp[0], qcur = qp[0];
    float vcur = vp[0], gcur = gp[0], bcur = bp[0];
    ks[0][wpos] = kcur; qs[0][wpos] = qcur;
    __syncthreads();

    for (int l = 0; l < SEQ; l++) {
        const int cur = l & 1, nxt = cur ^ 1;
        float knx = 0.f, qnx = 0.f, vnx = 0.f, gnx = 0.f, bnx = 0.f;
        if (l + 1 < SEQ) {
            knx = kp[(size_t)(l + 1) * 512];
            qnx = qp[(size_t)(l + 1) * 2048];
            vnx = vp[(size_t)(l + 1) * 512];
            gnx = gp[(size_t)(l + 1) * NH];
            bnx = bp[(size_t)(l + 1) * NH];
        }

        const float eg = expf(gcur);
        const unsigned long long eg2 = f2pack(eg, eg);
        const ulonglong2* k2p = reinterpret_cast<const ulonglong2*>(&ks[cur][kb * 68]);
        const ulonglong2* q2p = reinterpret_cast<const ulonglong2*>(&qs[cur][kb * 68]);

        unsigned long long kva = 0ull, kvb = 0ull;
        #pragma unroll
        for (int i = 0; i < 16; i++) {
            ulonglong2 kk = k2p[i];
            MUL2(S2[2 * i], S2[2 * i], eg2);
            FMA2(kva, kk.x, S2[2 * i], kva);
            MUL2(S2[2 * i + 1], S2[2 * i + 1], eg2);
            FMA2(kvb, kk.y, S2[2 * i + 1], kvb);
        }
        float kvp = f2sum(kva) + f2sum(kvb);
        kvp += __shfl_xor_sync(0xffffffffu, kvp, 1);
        const float cc = bcur * (vcur - kvp);
        const unsigned long long cc2 = f2pack(cc, cc);

        unsigned long long qa = 0ull, qb = 0ull;
        #pragma unroll
        for (int i = 0; i < 16; i++) {
            ulonglong2 kk = k2p[i];
            ulonglong2 qq = q2p[i];
            FMA2(S2[2 * i], kk.x, cc2, S2[2 * i]);
            FMA2(qa, qq.x, S2[2 * i], qa);
            FMA2(S2[2 * i + 1], kk.y, cc2, S2[2 * i + 1]);
            FMA2(qb, qq.y, S2[2 * i + 1], qb);
        }
        float qo = f2sum(qa) + f2sum(qb);
        qo += __shfl_xor_sync(0xffffffffu, qo, 1);
        if (kb == 0) op[(size_t)l * 2048] = qo;

        ks[nxt][wpos] = knx; qs[nxt][wpos] = qnx;
        __syncthreads();
        vcur = vnx; gcur = gnx; bcur = bnx;
    }
}

// ---------------------------------------------------------------------------
// FusedRMSNormGated -> fp16 hi/lo (gate from xcat col 3072+)
// ---------------------------------------------------------------------------
__global__ __launch_bounds__(128) void rmsgate_kernel(
    const float* __restrict__ xcat, const float* __restrict__ w)
{
    const int row = blockIdx.x;
    const int h   = blockIdx.y;
    const int t   = threadIdx.x;

    const size_t idx = (size_t)(row * NH + h) * DHEAD + t;
    float o = g_o[idx];

    float ss = o * o;
    #pragma unroll
    for (int off = 16; off > 0; off >>= 1)
        ss += __shfl_xor_sync(0xffffffffu, ss, off);
    __shared__ float sm[4];
    if ((t & 31) == 0) sm[t >> 5] = ss;
    __syncthreads();
    float tot = sm[0] + sm[1] + sm[2] + sm[3];
    float r = rsqrtf(tot * (1.f / 128.f) + 1e-5f);

    float gate = xcat[(size_t)row * NCAT + COL_G + h * DHEAD + t];
    float sg   = gate / (1.f + expf(-gate));
    float val  = o * r * w[t] * sg;

    size_t oo = (size_t)row * DH_ + h * DHEAD + t;
    __half hi = __float2half_rn(val);
    g_ofhi[oo] = hi;
    g_oflo[oo] = __float2half_rn(val - __half2float(hi));
}

// ---------------------------------------------------------------------------
// Launch (ordered so the fused projection GEMM is launch index 5 for ncu)
// ---------------------------------------------------------------------------
extern "C" void kernel_launch(void* const* d_in, const int* in_sizes, int n_in,
                              void* d_out, int out_size)
{
    (void)in_sizes; (void)n_in; (void)out_size;
    const float* x     = (const float*)d_in[0];
    const float* Wq    = (const float*)d_in[1];
    const float* Wk    = (const float*)d_in[2];
    const float* Wv    = (const float*)d_in[3];
    const float* Wb    = (const float*)d_in[4];
    const float* Wgk   = (const float*)d_in[5];
    const float* A_log = (const float*)d_in[6];
    const float* dt_b  = (const float*)d_in[7];
    const float* convq = (const float*)d_in[8];
    const float* convk = (const float*)d_in[9];
    const float* convv = (const float*)d_in[10];
    const float* Wg    = (const float*)d_in[11];
    const float* onw   = (const float*)d_in[12];
    const float* Wo    = (const float*)d_in[13];
    float* out = (float*)d_out;

    cudaFuncSetAttribute(gemm_mma, cudaFuncAttributeMaxDynamicSharedMemorySize, SM_GEMM);

    float *p_xcat, *p_q, *p_k, *p_v;
    __half *p_xhi, *p_xlo, *p_ofhi, *p_oflo, *p_wcat, *p_wot;
    cudaGetSymbolAddress((void**)&p_xcat, g_xcat);
    cudaGetSymbolAddress((void**)&p_q,  g_q);
    cudaGetSymbolAddress((void**)&p_k,  g_k);
    cudaGetSymbolAddress((void**)&p_v,  g_v);
    cudaGetSymbolAddress((void**)&p_xhi, g_xhi);
    cudaGetSymbolAddress((void**)&p_xlo, g_xlo);
    cudaGetSymbolAddress((void**)&p_ofhi, g_ofhi);
    cudaGetSymbolAddress((void**)&p_oflo, g_oflo);
    cudaGetSymbolAddress((void**)&p_wcat, g_wcat);
    cudaGetSymbolAddress((void**)&p_wot,  g_wot);

    // 0-4) conversions (5 launches -> gemm_mma is launch index 5)
    hilo_kernel<<<(ROWS * DH_ / 2 + 255) / 256, 256>>>(x, p_xhi, p_xlo, ROWS * DH_ / 2);
    transpose_f16<<<dim3(DH_/32, DH_/32), 256>>>(Wq, p_wcat,                       DH_, DH_);
    transpose_f16<<<dim3(512/32, DH_/32), 256>>>(Wk, p_wcat + (size_t)COL_K * DH_, DH_, 512);
    transpose_f16<<<dim3(512/32, DH_/32), 256>>>(Wv, p_wcat + (size_t)COL_V * DH_, DH_, 512);
    transpose_f16<<<dim3(DH_/32, DH_/32), 256>>>(Wg, p_wcat + (size_t)COL_G * DH_, DH_, DH_);

    // 5) fused projection GEMM: xcat[4096, 5120]   <-- ncu captures this
    gemm_mma<<<dim3(NCAT / 128, 32), 256, SM_GEMM>>>(p_xhi, p_xlo, p_wcat, p_xcat, NCAT, DH_);

    // 6) Wo transpose (only needed before the final GEMM)
    transpose_f16<<<dim3(DH_/32, DH_/32), 256>>>(Wo, p_wot, DH_, DH_);

    // 7) exact fp32 beta/g
    betag_kernel<<<ROWS, 256>>>(x, Wb, Wgk, A_log, dt_b);

    // 8-10) conv + silu (+ l2 norm; q scaled by D^-0.5)
    conv_kernel<<<dim3(ROWS, 16), 128>>>(p_xcat,         convq, p_q, 2048, 1, 0.08838834764831845f);
    conv_kernel<<<dim3(ROWS,  4), 128>>>(p_xcat + COL_K, convk, p_k,  512, 1, 1.f);
    conv_kernel<<<dim3(ROWS,  4), 128>>>(p_xcat + COL_V, convv, p_v,  512, 0, 1.f);

    // 11) recurrence (128 CTAs)
    recurrence_kernel<<<128, 128>>>();

    // 12) gated rmsnorm (-> fp16 hi/lo)
    rmsgate_kernel<<<dim3(ROWS, 16), 128>>>(p_xcat, onw);

    // 13) output projection
    gemm_mma<<<dim3(16, 32), 256, SM_GEMM>>>(p_ofhi, p_oflo, p_wot, out, 2048, DH_);
}

// round 7
// speedup vs baseline: 3.0737x; 1.1778x over previous
#include <cuda_runtime.h>
#include <cuda_fp16.h>
#include <math.h>
#include <stdint.h>

// ---------------------------------------------------------------------------
// Problem constants: B=4, L=1024, DH=2048, D=128, HQ=16, HK=HV=4, H=16, K=4
// Fused projection layout (columns of xcat / rows of wcat):
//   [0,2048) q | [2048,2560) k | [2560,3072) v | [3072,5120) g
// ---------------------------------------------------------------------------
#define ROWS 4096
#define DH_  2048
#define DHEAD 128
#define NH   16
#define NHK  4
#define SEQ  1024
#define NCAT 5120
#define COL_K 2048
#define COL_V 2560
#define COL_G 3072

// ---------------- device scratch (allocation-free rule) --------------------
__device__ float g_xcat[ROWS * NCAT];
__device__ float g_q [ROWS * DH_];
__device__ float g_k [ROWS * 512];
__device__ float g_v [ROWS * 512];
__device__ float g_beta[ROWS * NH];
__device__ float g_gd  [ROWS * NH];
__device__ float g_o [ROWS * DH_];

__device__ __align__(256) __half g_xhi[ROWS * DH_];
__device__ __align__(256) __half g_ofhi[ROWS * DH_];
__device__ __align__(256) __half g_oflo[ROWS * DH_];
__device__ __align__(256) __half g_wcat[NCAT * DH_];     // [N=5120, K=2048] fp16
__device__ __align__(256) __half g_wot[DH_ * DH_];       // Wo^T fp16

// ---------------------------------------------------------------------------
// PTX helpers (baseline ISA only)
// ---------------------------------------------------------------------------
__device__ __forceinline__ uint32_t smem_to_u32(const void* p) {
    uint32_t a;
    asm("{ .reg .u64 t; cvta.to.shared.u64 t, %1; cvt.u32.u64 %0, t; }"
        : "=r"(a) : "l"(p));
    return a;
}
__device__ __forceinline__ void cp16(uint32_t s, const void* g) {
    asm volatile("cp.async.cg.shared.global [%0], [%1], 16;"
                 :: "r"(s), "l"(g) : "memory");
}
#define CP_COMMIT() asm volatile("cp.async.commit_group;" ::: "memory")

#define LDSM4(d, addr) \
    asm volatile("ldmatrix.sync.aligned.m8n8.x4.shared.b16 {%0,%1,%2,%3}, [%4];" \
        : "=r"((d)[0]), "=r"((d)[1]), "=r"((d)[2]), "=r"((d)[3]) : "r"(addr))

#define MMA16816F(c, a, b) \
    asm volatile("mma.sync.aligned.m16n8k16.row.col.f32.f16.f16.f32 " \
        "{%0,%1,%2,%3}, {%4,%5,%6,%7}, {%8,%9}, {%0,%1,%2,%3};" \
        : "+f"((c)[0]), "+f"((c)[1]), "+f"((c)[2]), "+f"((c)[3]) \
        : "r"((a)[0]), "r"((a)[1]), "r"((a)[2]), "r"((a)[3]), \
          "r"((b)[0]), "r"((b)[1]))

// ---------------------------------------------------------------------------
// fp32 -> fp16 convert (A of projection GEMM; single rounding)
// ---------------------------------------------------------------------------
__global__ __launch_bounds__(256) void tof16_kernel(
    const float* __restrict__ in, __half* __restrict__ out, int n2)
{
    int i = blockIdx.x * 256 + threadIdx.x;
    if (i >= n2) return;
    float2 v = ((const float2*)in)[i];
    ((__half2*)out)[i] = __halves2half2(__float2half_rn(v.x), __float2half_rn(v.y));
}

// ---------------------------------------------------------------------------
// Fused weight transposes: Wq|Wk|Wv|Wg -> wcat [5120,2048] fp16; Wo -> wot.
// 32x32 tiles, 14336 total blocks.
// ---------------------------------------------------------------------------
__global__ __launch_bounds__(256) void transpose_all(
    const float* __restrict__ Wq, const float* __restrict__ Wk,
    const float* __restrict__ Wv, const float* __restrict__ Wg,
    const float* __restrict__ Wo,
    __half* __restrict__ wcat, __half* __restrict__ wot)
{
    __shared__ float t[32][33];
    const int idx = blockIdx.x;
    const float* W; __half* T; int N, bx, by;
    if (idx < 4096)        { W = Wq; T = wcat;                        N = 2048; int l = idx;         bx = l & 63; by = l >> 6; }
    else if (idx < 5120)   { W = Wk; T = wcat + (size_t)COL_K * DH_;  N =  512; int l = idx - 4096;  bx = l & 15; by = l >> 4; }
    else if (idx < 6144)   { W = Wv; T = wcat + (size_t)COL_V * DH_;  N =  512; int l = idx - 5120;  bx = l & 15; by = l >> 4; }
    else if (idx < 10240)  { W = Wg; T = wcat + (size_t)COL_G * DH_;  N = 2048; int l = idx - 6144;  bx = l & 63; by = l >> 6; }
    else                   { W = Wo; T = wot;                         N = 2048; int l = idx - 10240; bx = l & 63; by = l >> 6; }
    bx <<= 5; by <<= 5;
    const int tx = threadIdx.x & 31, ty = threadIdx.x >> 5;
    #pragma unroll
    for (int i = 0; i < 32; i += 8)
        t[ty + i][tx] = W[(size_t)(by + ty + i) * N + bx + tx];
    __syncthreads();
    #pragma unroll
    for (int i = 0; i < 32; i += 8)
        T[(size_t)(bx + ty + i) * DH_ + by + tx] = __float2half_rn(t[tx][ty + i]);
}

// ---------------------------------------------------------------------------
// Exact fp32 beta/g as a thin GEMM: 8 rows/CTA staged in smem, lane = column.
// beta = sigmoid(x@Wb), g = -exp(A_log)*softplus(x@Wgk + dt_bias)
// ---------------------------------------------------------------------------
__global__ __launch_bounds__(256) void betag_fast(
    const float* __restrict__ x, const float* __restrict__ Wb,
    const float* __restrict__ Wgk, const float* __restrict__ A_log,
    const float* __restrict__ dt_bias)
{
    extern __shared__ float xs[];                 // 8 * 2048 floats = 64KB
    const int row0 = blockIdx.x * 8;
    const float4* xin = (const float4*)(x + (size_t)row0 * DH_);
    float4* xs4 = (float4*)xs;
    for (int i = threadIdx.x; i < 8 * DH_ / 4; i += 256) xs4[i] = xin[i];
    __syncthreads();

    const int ty   = threadIdx.x >> 5;            // row 0..7
    const int lane = threadIdx.x & 31;
    const int col  = lane & 15;
    const float* W = (lane < 16) ? Wb : Wgk;
    const float* xr = xs + ty * DH_;

    float s0 = 0.f, s1 = 0.f, s2 = 0.f, s3 = 0.f;
    for (int k = 0; k < DH_; k += 4) {
        s0 = fmaf(xr[k + 0], W[(k + 0) * NH + col], s0);
        s1 = fmaf(xr[k + 1], W[(k + 1) * NH + col], s1);
        s2 = fmaf(xr[k + 2], W[(k + 2) * NH + col], s2);
        s3 = fmaf(xr[k + 3], W[(k + 3) * NH + col], s3);
    }
    float s = (s0 + s1) + (s2 + s3);
    const int row = row0 + ty;
    if (lane < 16) {
        g_beta[row * NH + col] = 1.f / (1.f + expf(-s));
    } else {
        float xg = s + dt_bias[col];
        float sp = (xg > 15.f) ? xg : log1pf(expf(xg));
        g_gd[row * NH + col] = -expf(A_log[col]) * sp;
    }
}

// ---------------------------------------------------------------------------
// GEMM 1-pass fp16: C[M,N] = A[M,K] @ B[N,K]^T, fp32 accumulate.
// BM=BN=128, BK=32, 4 stages of 16KB, 256 thr, 2 CTAs/SM.
// ---------------------------------------------------------------------------
#define ST1 16384
#define SM1 (4 * ST1)

__global__ __launch_bounds__(256, 2) void gemm1(
    const __half* __restrict__ A, const __half* __restrict__ B,
    float* __restrict__ C, int N, int K)
{
    extern __shared__ char smem[];
    const uint32_t sb = smem_to_u32(smem);
    const int tid  = threadIdx.x;
    const int lane = tid & 31;
    const int wid  = tid >> 5;
    const int wm   = wid & 1;
    const int wn   = wid >> 1;
    const int brow = blockIdx.y * 128;
    const int bcol = blockIdx.x * 128;
    const size_t K2 = (size_t)K * 2;

    uint32_t swo[2];
    size_t   ga[2], gb[2];
    #pragma unroll
    for (int i = 0; i < 2; i++) {
        int c  = tid + (i << 8);
        int r  = c >> 2, ch = c & 3;
        swo[i] = (uint32_t)(r * 64 + ((ch ^ ((r >> 1) & 3)) << 4));
        ga[i]  = (size_t)(brow + r) * K2 + (size_t)(ch << 4);
        gb[i]  = (size_t)(bcol + r) * K2 + (size_t)(ch << 4);
    }

    const int NK = K >> 5;
    #pragma unroll
    for (int pf = 0; pf < 3; pf++) {
        uint32_t s0 = sb + pf * ST1;
        size_t ko = (size_t)pf << 6;
        #pragma unroll
        for (int i = 0; i < 2; i++) {
            cp16(s0 +    0 + swo[i], (const char*)A + ga[i] + ko);
            cp16(s0 + 8192 + swo[i], (const char*)B + gb[i] + ko);
        }
        CP_COMMIT();
    }

    float acc[4][4][4];
    #pragma unroll
    for (int mi = 0; mi < 4; mi++)
        #pragma unroll
        for (int ni = 0; ni < 4; ni++)
            #pragma unroll
            for (int j = 0; j < 4; j++) acc[mi][ni][j] = 0.f;

    int st_load = 3, st_cmp = 0;
    for (int kt = 0; kt < NK; kt++) {
        if (kt + 3 < NK) {
            uint32_t s0 = sb + st_load * ST1;
            size_t ko = (size_t)(kt + 3) << 6;
            #pragma unroll
            for (int i = 0; i < 2; i++) {
                cp16(s0 +    0 + swo[i], (const char*)A + ga[i] + ko);
                cp16(s0 + 8192 + swo[i], (const char*)B + gb[i] + ko);
            }
            CP_COMMIT();
            if (++st_load == 4) st_load = 0;
        }
        int ahead = NK - 1 - kt; if (ahead > 3) ahead = 3;
        if (ahead == 3)      asm volatile("cp.async.wait_group 3;" ::: "memory");
        else if (ahead == 2) asm volatile("cp.async.wait_group 2;" ::: "memory");
        else if (ahead == 1) asm volatile("cp.async.wait_group 1;" ::: "memory");
        else                 asm volatile("cp.async.wait_group 0;" ::: "memory");
        __syncthreads();

        const uint32_t sa = sb + st_cmp * ST1;
        #pragma unroll
        for (int ks = 0; ks < 2; ks++) {
            uint32_t ah[4][4];
            const int chA = (ks << 1) + (lane >> 4);
            #pragma unroll
            for (int mi = 0; mi < 4; mi++) {
                int r = wm * 64 + mi * 16 + (lane & 15);
                uint32_t ad = sa + (uint32_t)(r * 64 + ((chA ^ ((r >> 1) & 3)) << 4));
                LDSM4(ah[mi], ad);
            }
            uint32_t bh[4][2];
            #pragma unroll
            for (int nb = 0; nb < 2; nb++) {
                int r = wn * 32 + nb * 16 + (lane & 15);
                uint32_t bd = sa + 8192u + (uint32_t)(r * 64 + ((chA ^ ((r >> 1) & 3)) << 4));
                uint32_t d[4];
                LDSM4(d, bd);
                bh[2*nb][0] = d[0];   bh[2*nb][1] = d[2];
                bh[2*nb+1][0] = d[1]; bh[2*nb+1][1] = d[3];
            }
            #pragma unroll
            for (int mi = 0; mi < 4; mi++)
                #pragma unroll
                for (int ni = 0; ni < 4; ni++)
                    MMA16816F(acc[mi][ni], ah[mi], bh[ni]);
        }
        __syncthreads();
        if (++st_cmp == 4) st_cmp = 0;
    }

    #pragma unroll
    for (int mi = 0; mi < 4; mi++) {
        int r0 = brow + wm * 64 + mi * 16 + (lane >> 2);
        #pragma unroll
        for (int ni = 0; ni < 4; ni++) {
            int c0 = bcol + wn * 32 + ni * 8 + ((lane & 3) << 1);
            *(float2*)&C[(size_t)r0 * N + c0] =
                make_float2(acc[mi][ni][0], acc[mi][ni][1]);
            *(float2*)&C[(size_t)(r0 + 8) * N + c0] =
                make_float2(acc[mi][ni][2], acc[mi][ni][3]);
        }
    }
}

// ---------------------------------------------------------------------------
// GEMM 2-pass (A hi/lo fp16):  C = (Ahi+Alo) @ B^T  (output projection)
// ---------------------------------------------------------------------------
#define ST2 24576
#define SM2 (4 * ST2)

__global__ __launch_bounds__(256, 2) void gemm2(
    const __half* __restrict__ Ahi, const __half* __restrict__ Alo,
    const __half* __restrict__ B,
    float* __restrict__ C, int N, int K)
{
    extern __shared__ char smem[];
    const uint32_t sb = smem_to_u32(smem);
    const int tid  = threadIdx.x;
    const int lane = tid & 31;
    const int wid  = tid >> 5;
    const int wm   = wid & 1;
    const int wn   = wid >> 1;
    const int brow = blockIdx.y * 128;
    const int bcol = blockIdx.x * 128;
    const size_t K2 = (size_t)K * 2;

    uint32_t swo[2];
    size_t   ga[2], gb[2];
    #pragma unroll
    for (int i = 0; i < 2; i++) {
        int c  = tid + (i << 8);
        int r  = c >> 2, ch = c & 3;
        swo[i] = (uint32_t)(r * 64 + ((ch ^ ((r >> 1) & 3)) << 4));
        ga[i]  = (size_t)(brow + r) * K2 + (size_t)(ch << 4);
        gb[i]  = (size_t)(bcol + r) * K2 + (size_t)(ch << 4);
    }

    const int NK = K >> 5;
    #pragma unroll
    for (int pf = 0; pf < 3; pf++) {
        uint32_t s0 = sb + pf * ST2;
        size_t ko = (size_t)pf << 6;
        #pragma unroll
        for (int i = 0; i < 2; i++) {
            cp16(s0 +     0 + swo[i], (const char*)Ahi + ga[i] + ko);
            cp16(s0 +  8192 + swo[i], (const char*)Alo + ga[i] + ko);
            cp16(s0 + 16384 + swo[i], (const char*)B   + gb[i] + ko);
        }
        CP_COMMIT();
    }

    float acc[4][4][4];
    #pragma unroll
    for (int mi = 0; mi < 4; mi++)
        #pragma unroll
        for (int ni = 0; ni < 4; ni++)
            #pragma unroll
            for (int j = 0; j < 4; j++) acc[mi][ni][j] = 0.f;

    int st_load = 3, st_cmp = 0;
    for (int kt = 0; kt < NK; kt++) {
        if (kt + 3 < NK) {
            uint32_t s0 = sb + st_load * ST2;
            size_t ko = (size_t)(kt + 3) << 6;
            #pragma unroll
            for (int i = 0; i < 2; i++) {
                cp16(s0 +     0 + swo[i], (const char*)Ahi + ga[i] + ko);
                cp16(s0 +  8192 + swo[i], (const char*)Alo + ga[i] + ko);
                cp16(s0 + 16384 + swo[i], (const char*)B   + gb[i] + ko);
            }
            CP_COMMIT();
            if (++st_load == 4) st_load = 0;
        }
        int ahead = NK - 1 - kt; if (ahead > 3) ahead = 3;
        if (ahead == 3)      asm volatile("cp.async.wait_group 3;" ::: "memory");
        else if (ahead == 2) asm volatile("cp.async.wait_group 2;" ::: "memory");
        else if (ahead == 1) asm volatile("cp.async.wait_group 1;" ::: "memory");
        else                 asm volatile("cp.async.wait_group 0;" ::: "memory");
        __syncthreads();

        const uint32_t sa = sb + st_cmp * ST2;
        #pragma unroll
        for (int ks = 0; ks < 2; ks++) {
            uint32_t ah[4][4], al[4][4];
            const int chA = (ks << 1) + (lane >> 4);
            #pragma unroll
            for (int mi = 0; mi < 4; mi++) {
                int r = wm * 64 + mi * 16 + (lane & 15);
                uint32_t ad = sa + (uint32_t)(r * 64 + ((chA ^ ((r >> 1) & 3)) << 4));
                LDSM4(ah[mi], ad);
                LDSM4(al[mi], ad + 8192);
            }
            uint32_t bh[4][2];
            #pragma unroll
            for (int nb = 0; nb < 2; nb++) {
                int r = wn * 32 + nb * 16 + (lane & 15);
                uint32_t bd = sa + 16384u + (uint32_t)(r * 64 + ((chA ^ ((r >> 1) & 3)) << 4));
                uint32_t d[4];
                LDSM4(d, bd);
                bh[2*nb][0] = d[0];   bh[2*nb][1] = d[2];
                bh[2*nb+1][0] = d[1]; bh[2*nb+1][1] = d[3];
            }
            #pragma unroll
            for (int mi = 0; mi < 4; mi++)
                #pragma unroll
                for (int ni = 0; ni < 4; ni++) {
                    MMA16816F(acc[mi][ni], ah[mi], bh[ni]);
                    MMA16816F(acc[mi][ni], al[mi], bh[ni]);
                }
        }
        __syncthreads();
        if (++st_cmp == 4) st_cmp = 0;
    }

    #pragma unroll
    for (int mi = 0; mi < 4; mi++) {
        int r0 = brow + wm * 64 + mi * 16 + (lane >> 2);
        #pragma unroll
        for (int ni = 0; ni < 4; ni++) {
            int c0 = bcol + wn * 32 + ni * 8 + ((lane & 3) << 1);
            *(float2*)&C[(size_t)r0 * N + c0] =
                make_float2(acc[mi][ni][0], acc[mi][ni][1]);
            *(float2*)&C[(size_t)(r0 + 8) * N + c0] =
                make_float2(acc[mi][ni][2], acc[mi][ni][3]);
        }
    }
}

// ---------------------------------------------------------------------------
// Causal depthwise conv (K=4) + SiLU (+ optional L2 norm * scale)
// ---------------------------------------------------------------------------
__global__ __launch_bounds__(128) void conv_kernel(
    const float* __restrict__ in, const float* __restrict__ w,
    float* __restrict__ out, int chans, int do_l2, float scale)
{
    const int row = blockIdx.x;
    const int c   = blockIdx.y * DHEAD + threadIdx.x;
    const int l   = row & (SEQ - 1);

    float acc = 0.f;
    #pragma unroll
    for (int j = 0; j < 4; j++) {
        int sl = l + j - 3;
        if (sl >= 0) acc += in[(size_t)(row + j - 3) * NCAT + c] * w[c * 4 + j];
    }
    float y = acc / (1.f + expf(-acc));

    if (do_l2) {
        __shared__ float sm[4];
        float ss = y * y;
        #pragma unroll
        for (int off = 16; off > 0; off >>= 1)
            ss += __shfl_xor_sync(0xffffffffu, ss, off);
        if ((threadIdx.x & 31) == 0) sm[threadIdx.x >> 5] = ss;
        __syncthreads();
        float tot = sm[0] + sm[1] + sm[2] + sm[3];
        y *= rsqrtf(tot + 1e-6f) * scale;
    }
    out[(size_t)row * chans + c] = y;
}

// ---------------------------------------------------------------------------
// Gated delta-rule recurrence, f32x2-packed, 128 CTAs.
// ---------------------------------------------------------------------------
#define FMA2(d, a, b, c) \
    asm("fma.rn.f32x2 %0, %1, %2, %3;" : "=l"(d) : "l"(a), "l"(b), "l"(c))
#define MUL2(d, a, b) \
    asm("mul.rn.f32x2 %0, %1, %2;" : "=l"(d) : "l"(a), "l"(b))

__device__ __forceinline__ unsigned long long f2pack(float a, float b) {
    unsigned long long r;
    asm("mov.b64 %0, {%1, %2};" : "=l"(r)
        : "r"(__float_as_uint(a)), "r"(__float_as_uint(b)));
    return r;
}
__device__ __forceinline__ float f2sum(unsigned long long v) {
    uint32_t x, y;
    asm("mov.b64 {%0, %1}, %2;" : "=r"(x), "=r"(y) : "l"(v));
    return __uint_as_float(x) + __uint_as_float(y);
}

__global__ __launch_bounds__(128) void recurrence_kernel()
{
    __shared__ __align__(16) float ks[2][136];
    __shared__ __align__(16) float qs[2][136];

    const int bx   = blockIdx.x;
    const int pair = bx >> 1;
    const int half = bx & 1;
    const int b  = pair >> 4;
    const int h  = pair & 15;
    const int kh = h >> 2;
    const int t  = threadIdx.x;
    const int col = half * 64 + (t >> 1);
    const int kb  = t & 1;
    const int wpos = (t < 64) ? t : t + 4;

    unsigned long long S2[32];
    #pragma unroll
    for (int d = 0; d < 32; d++) S2[d] = 0ull;

    const float* qp = g_q    + ((size_t)(b * SEQ) * NH  + h ) * DHEAD + t;
    const float* kp = g_k    + ((size_t)(b * SEQ) * NHK + kh) * DHEAD + t;
    const float* vp = g_v    + ((size_t)(b * SEQ) * NHK + kh) * DHEAD + col;
    const float* gp = g_gd   +  (size_t)(b * SEQ) * NH + h;
    const float* bp = g_beta +  (size_t)(b * SEQ) * NH + h;
    float*       op = g_o    + ((size_t)(b * SEQ) * NH  + h ) * DHEAD + col;

    float kcur = kp[0], qcur = qp[0];
    float vcur = vp[0], gcur = gp[0], bcur = bp[0];
    ks[0][wpos] = kcur; qs[0][wpos] = qcur;
    __syncthreads();

    for (int l = 0; l < SEQ; l++) {
        const int cur = l & 1, nxt = cur ^ 1;
        float knx = 0.f, qnx = 0.f, vnx = 0.f, gnx = 0.f, bnx = 0.f;
        if (l + 1 < SEQ) {
            knx = kp[(size_t)(l + 1) * 512];
            qnx = qp[(size_t)(l + 1) * 2048];
            vnx = vp[(size_t)(l + 1) * 512];
            gnx = gp[(size_t)(l + 1) * NH];
            bnx = bp[(size_t)(l + 1) * NH];
        }

        const float eg = expf(gcur);
        const unsigned long long eg2 = f2pack(eg, eg);
        const ulonglong2* k2p = reinterpret_cast<const ulonglong2*>(&ks[cur][kb * 68]);
        const ulonglong2* q2p = reinterpret_cast<const ulonglong2*>(&qs[cur][kb * 68]);

        unsigned long long kva = 0ull, kvb = 0ull;
        #pragma unroll
        for (int i = 0; i < 16; i++) {
            ulonglong2 kk = k2p[i];
            MUL2(S2[2 * i], S2[2 * i], eg2);
            FMA2(kva, kk.x, S2[2 * i], kva);
            MUL2(S2[2 * i + 1], S2[2 * i + 1], eg2);
            FMA2(kvb, kk.y, S2[2 * i + 1], kvb);
        }
        float kvp = f2sum(kva) + f2sum(kvb);
        kvp += __shfl_xor_sync(0xffffffffu, kvp, 1);
        const float cc = bcur * (vcur - kvp);
        const unsigned long long cc2 = f2pack(cc, cc);

        unsigned long long qa = 0ull, qb = 0ull;
        #pragma unroll
        for (int i = 0; i < 16; i++) {
            ulonglong2 kk = k2p[i];
            ulonglong2 qq = q2p[i];
            FMA2(S2[2 * i], kk.x, cc2, S2[2 * i]);
            FMA2(qa, qq.x, S2[2 * i], qa);
            FMA2(S2[2 * i + 1], kk.y, cc2, S2[2 * i + 1]);
            FMA2(qb, qq.y, S2[2 * i + 1], qb);
        }
        float qo = f2sum(qa) + f2sum(qb);
        qo += __shfl_xor_sync(0xffffffffu, qo, 1);
        if (kb == 0) op[(size_t)l * 2048] = qo;

        ks[nxt][wpos] = knx; qs[nxt][wpos] = qnx;
        __syncthreads();
        vcur = vnx; gcur = gnx; bcur = bnx;
    }
}

// ---------------------------------------------------------------------------
// FusedRMSNormGated -> fp16 hi/lo (gate from xcat col 3072+)
// ---------------------------------------------------------------------------
__global__ __launch_bounds__(128) void rmsgate_kernel(
    const float* __restrict__ xcat, const float* __restrict__ w)
{
    const int row = blockIdx.x;
    const int h   = blockIdx.y;
    const int t   = threadIdx.x;

    const size_t idx = (size_t)(row * NH + h) * DHEAD + t;
    float o = g_o[idx];

    float ss = o * o;
    #pragma unroll
    for (int off = 16; off > 0; off >>= 1)
        ss += __shfl_xor_sync(0xffffffffu, ss, off);
    __shared__ float sm[4];
    if ((t & 31) == 0) sm[t >> 5] = ss;
    __syncthreads();
    float tot = sm[0] + sm[1] + sm[2] + sm[3];
    float r = rsqrtf(tot * (1.f / 128.f) + 1e-5f);

    float gate = xcat[(size_t)row * NCAT + COL_G + h * DHEAD + t];
    float sg   = gate / (1.f + expf(-gate));
    float val  = o * r * w[t] * sg;

    size_t oo = (size_t)row * DH_ + h * DHEAD + t;
    __half hi = __float2half_rn(val);
    g_ofhi[oo] = hi;
    g_oflo[oo] = __float2half_rn(val - __half2float(hi));
}

// ---------------------------------------------------------------------------
// Launch (gemm1 is our 4th launch -> lands in the ncu capture window)
// ---------------------------------------------------------------------------
extern "C" void kernel_launch(void* const* d_in, const int* in_sizes, int n_in,
                              void* d_out, int out_size)
{
    (void)in_sizes; (void)n_in; (void)out_size;
    const float* x     = (const float*)d_in[0];
    const float* Wq    = (const float*)d_in[1];
    const float* Wk    = (const float*)d_in[2];
    const float* Wv    = (const float*)d_in[3];
    const float* Wb    = (const float*)d_in[4];
    const float* Wgk   = (const float*)d_in[5];
    const float* A_log = (const float*)d_in[6];
    const float* dt_b  = (const float*)d_in[7];
    const float* convq = (const float*)d_in[8];
    const float* convk = (const float*)d_in[9];
    const float* convv = (const float*)d_in[10];
    const float* Wg    = (const float*)d_in[11];
    const float* onw   = (const float*)d_in[12];
    const float* Wo    = (const float*)d_in[13];
    float* out = (float*)d_out;

    cudaFuncSetAttribute(gemm1, cudaFuncAttributeMaxDynamicSharedMemorySize, SM1);
    cudaFuncSetAttribute(gemm2, cudaFuncAttributeMaxDynamicSharedMemorySize, SM2);
    cudaFuncSetAttribute(betag_fast, cudaFuncAttributeMaxDynamicSharedMemorySize, 65536);

    float *p_xcat, *p_q, *p_k, *p_v;
    __half *p_xhi, *p_ofhi, *p_oflo, *p_wcat, *p_wot;
    cudaGetSymbolAddress((void**)&p_xcat, g_xcat);
    cudaGetSymbolAddress((void**)&p_q,  g_q);
    cudaGetSymbolAddress((void**)&p_k,  g_k);
    cudaGetSymbolAddress((void**)&p_v,  g_v);
    cudaGetSymbolAddress((void**)&p_xhi, g_xhi);
    cudaGetSymbolAddress((void**)&p_ofhi, g_ofhi);
    cudaGetSymbolAddress((void**)&p_oflo, g_oflo);
    cudaGetSymbolAddress((void**)&p_wcat, g_wcat);
    cudaGetSymbolAddress((void**)&p_wot,  g_wot);

    // 1) x -> fp16
    tof16_kernel<<<(ROWS * DH_ / 2 + 255) / 256, 256>>>(x, p_xhi, ROWS * DH_ / 2);
    // 2) all weight transposes (fused)
    transpose_all<<<14336, 256>>>(Wq, Wk, Wv, Wg, Wo, p_wcat, p_wot);
    // 3) exact fp32 beta/g (thin GEMM)
    betag_fast<<<ROWS / 8, 256, 65536>>>(x, Wb, Wgk, A_log, dt_b);
    // 4) fused projection GEMM (single-pass fp16)   <-- ncu capture target
    gemm1<<<dim3(NCAT / 128, 32), 256, SM1>>>(p_xhi, p_wcat, p_xcat, NCAT, DH_);
    // 5-7) conv + silu (+ l2 norm; q scaled by D^-0.5)
    conv_kernel<<<dim3(ROWS, 16), 128>>>(p_xcat,         convq, p_q, 2048, 1, 0.08838834764831845f);
    conv_kernel<<<dim3(ROWS,  4), 128>>>(p_xcat + COL_K, convk, p_k,  512, 1, 1.f);
    conv_kernel<<<dim3(ROWS,  4), 128>>>(p_xcat + COL_V, convv, p_v,  512, 0, 1.f);
    // 8) recurrence
    recurrence_kernel<<<128, 128>>>();
    // 9) gated rmsnorm (-> fp16 hi/lo)
    rmsgate_kernel<<<dim3(ROWS, 16), 128>>>(p_xcat, onw);
    // 10) output projection (2-pass, precision-compensated)
    gemm2<<<dim3(16, 32), 256, SM2>>>(p_ofhi, p_oflo, p_wot, out, 2048, DH_);
}

// round 8
// speedup vs baseline: 3.3992x; 1.1059x over previous
#include <cuda_runtime.h>
#include <cuda_fp16.h>
#include <math.h>
#include <stdint.h>

// ---------------------------------------------------------------------------
// Problem constants: B=4, L=1024, DH=2048, D=128, HQ=16, HK=HV=4, H=16, K=4
// Fused projection layout (columns of xcat / rows of wcat):
//   [0,2048) q | [2048,2560) k | [2560,3072) v | [3072,5120) g
// ---------------------------------------------------------------------------
#define ROWS 4096
#define DH_  2048
#define DHEAD 128
#define NH   16
#define NHK  4
#define SEQ  1024
#define NCAT 5120
#define COL_K 2048
#define COL_V 2560
#define COL_G 3072

// ---------------- device scratch (allocation-free rule) --------------------
__device__ float g_xcat[ROWS * NCAT];
__device__ float g_q [ROWS * DH_];
__device__ float g_k [ROWS * 512];
__device__ float g_v [ROWS * 512];
__device__ float g_beta[ROWS * NH];
__device__ float g_gd  [ROWS * NH];
__device__ float g_o [ROWS * DH_];

__device__ __align__(256) __half g_xhi[ROWS * DH_];
__device__ __align__(256) __half g_of [ROWS * DH_];
__device__ __align__(256) __half g_wcat[NCAT * DH_];     // [N=5120, K=2048] fp16
__device__ __align__(256) __half g_wot[DH_ * DH_];       // Wo^T fp16

// ---------------------------------------------------------------------------
// PTX helpers (baseline ISA only)
// ---------------------------------------------------------------------------
__device__ __forceinline__ uint32_t smem_to_u32(const void* p) {
    uint32_t a;
    asm("{ .reg .u64 t; cvta.to.shared.u64 t, %1; cvt.u32.u64 %0, t; }"
        : "=r"(a) : "l"(p));
    return a;
}
__device__ __forceinline__ void cp16(uint32_t s, const void* g) {
    asm volatile("cp.async.cg.shared.global [%0], [%1], 16;"
                 :: "r"(s), "l"(g) : "memory");
}
#define CP_COMMIT() asm volatile("cp.async.commit_group;" ::: "memory")

#define LDSM4(d, addr) \
    asm volatile("ldmatrix.sync.aligned.m8n8.x4.shared.b16 {%0,%1,%2,%3}, [%4];" \
        : "=r"((d)[0]), "=r"((d)[1]), "=r"((d)[2]), "=r"((d)[3]) : "r"(addr))

#define MMA16816F(c, a, b) \
    asm volatile("mma.sync.aligned.m16n8k16.row.col.f32.f16.f16.f32 " \
        "{%0,%1,%2,%3}, {%4,%5,%6,%7}, {%8,%9}, {%0,%1,%2,%3};" \
        : "+f"((c)[0]), "+f"((c)[1]), "+f"((c)[2]), "+f"((c)[3]) \
        : "r"((a)[0]), "r"((a)[1]), "r"((a)[2]), "r"((a)[3]), \
          "r"((b)[0]), "r"((b)[1]))

// ---------------------------------------------------------------------------
// fp32 -> fp16 convert (A of projection GEMM; single rounding)
// ---------------------------------------------------------------------------
__global__ __launch_bounds__(256) void tof16_kernel(
    const float* __restrict__ in, __half* __restrict__ out, int n2)
{
    int i = blockIdx.x * 256 + threadIdx.x;
    if (i >= n2) return;
    float2 v = ((const float2*)in)[i];
    ((__half2*)out)[i] = __halves2half2(__float2half_rn(v.x), __float2half_rn(v.y));
}

// ---------------------------------------------------------------------------
// Fused weight transposes: Wq|Wk|Wv|Wg -> wcat [5120,2048] fp16; Wo -> wot.
// ---------------------------------------------------------------------------
__global__ __launch_bounds__(256) void transpose_all(
    const float* __restrict__ Wq, const float* __restrict__ Wk,
    const float* __restrict__ Wv, const float* __restrict__ Wg,
    const float* __restrict__ Wo,
    __half* __restrict__ wcat, __half* __restrict__ wot)
{
    __shared__ float t[32][33];
    const int idx = blockIdx.x;
    const float* W; __half* T; int N, bx, by;
    if (idx < 4096)        { W = Wq; T = wcat;                        N = 2048; int l = idx;         bx = l & 63; by = l >> 6; }
    else if (idx < 5120)   { W = Wk; T = wcat + (size_t)COL_K * DH_;  N =  512; int l = idx - 4096;  bx = l & 15; by = l >> 4; }
    else if (idx < 6144)   { W = Wv; T = wcat + (size_t)COL_V * DH_;  N =  512; int l = idx - 5120;  bx = l & 15; by = l >> 4; }
    else if (idx < 10240)  { W = Wg; T = wcat + (size_t)COL_G * DH_;  N = 2048; int l = idx - 6144;  bx = l & 63; by = l >> 6; }
    else                   { W = Wo; T = wot;                         N = 2048; int l = idx - 10240; bx = l & 63; by = l >> 6; }
    bx <<= 5; by <<= 5;
    const int tx = threadIdx.x & 31, ty = threadIdx.x >> 5;
    #pragma unroll
    for (int i = 0; i < 32; i += 8)
        t[ty + i][tx] = W[(size_t)(by + ty + i) * N + bx + tx];
    __syncthreads();
    #pragma unroll
    for (int i = 0; i < 32; i += 8)
        T[(size_t)(bx + ty + i) * DH_ + by + tx] = __float2half_rn(t[tx][ty + i]);
}

// ---------------------------------------------------------------------------
// Exact fp32 beta/g as a thin GEMM: 8 rows/CTA staged in smem, lane = column.
// ---------------------------------------------------------------------------
__global__ __launch_bounds__(256) void betag_fast(
    const float* __restrict__ x, const float* __restrict__ Wb,
    const float* __restrict__ Wgk, const float* __restrict__ A_log,
    const float* __restrict__ dt_bias)
{
    extern __shared__ float xs[];                 // 8 * 2048 floats = 64KB
    const int row0 = blockIdx.x * 8;
    const float4* xin = (const float4*)(x + (size_t)row0 * DH_);
    float4* xs4 = (float4*)xs;
    for (int i = threadIdx.x; i < 8 * DH_ / 4; i += 256) xs4[i] = xin[i];
    __syncthreads();

    const int ty   = threadIdx.x >> 5;
    const int lane = threadIdx.x & 31;
    const int col  = lane & 15;
    const float* W = (lane < 16) ? Wb : Wgk;
    const float* xr = xs + ty * DH_;

    float s0 = 0.f, s1 = 0.f, s2 = 0.f, s3 = 0.f;
    for (int k = 0; k < DH_; k += 4) {
        s0 = fmaf(xr[k + 0], W[(k + 0) * NH + col], s0);
        s1 = fmaf(xr[k + 1], W[(k + 1) * NH + col], s1);
        s2 = fmaf(xr[k + 2], W[(k + 2) * NH + col], s2);
        s3 = fmaf(xr[k + 3], W[(k + 3) * NH + col], s3);
    }
    float s = (s0 + s1) + (s2 + s3);
    const int row = row0 + ty;
    if (lane < 16) {
        g_beta[row * NH + col] = 1.f / (1.f + expf(-s));
    } else {
        float xg = s + dt_bias[col];
        float sp = (xg > 15.f) ? xg : log1pf(expf(xg));
        g_gd[row * NH + col] = -expf(A_log[col]) * sp;
    }
}

// ---------------------------------------------------------------------------
// 1-pass fp16 GEMM: C[M,N] = A[M,K] @ B[N,K]^T, fp32 accumulate.
// BM=BN=128, BK=64 (128B rows), 3 stages of 32KB (96KB), 256 thr, 2 CTAs/SM.
// ---------------------------------------------------------------------------
#define ST1 32768          // A 16K | B 16K
#define SM1 (3 * ST1)

__global__ __launch_bounds__(256, 2) void gemm1(
    const __half* __restrict__ A, const __half* __restrict__ B,
    float* __restrict__ C, int N, int K)
{
    extern __shared__ char smem[];
    const uint32_t sb = smem_to_u32(smem);
    const int tid  = threadIdx.x;
    const int lane = tid & 31;
    const int wid  = tid >> 5;
    const int wm   = wid & 1;
    const int wn   = wid >> 1;
    const int brow = blockIdx.y * 128;
    const int bcol = blockIdx.x * 128;
    const size_t K2 = (size_t)K * 2;

    // 4 x 16B per 16KB buffer per thread (128 rows x 8 chunks)
    uint32_t swo[4];
    size_t   ga[4], gb[4];
    #pragma unroll
    for (int i = 0; i < 4; i++) {
        int c  = tid + (i << 8);       // 0..1023
        int r  = c >> 3, ch = c & 7;
        swo[i] = (uint32_t)(r * 128 + ((ch ^ (r & 7)) << 4));
        ga[i]  = (size_t)(brow + r) * K2 + (size_t)(ch << 4);
        gb[i]  = (size_t)(bcol + r) * K2 + (size_t)(ch << 4);
    }

    const int NK = K >> 6;   // BK=64
    #pragma unroll
    for (int pf = 0; pf < 2; pf++) {
        uint32_t s0 = sb + pf * ST1;
        size_t ko = (size_t)pf << 7;   // kt*128 bytes
        #pragma unroll
        for (int i = 0; i < 4; i++) {
            cp16(s0 +     0 + swo[i], (const char*)A + ga[i] + ko);
            cp16(s0 + 16384 + swo[i], (const char*)B + gb[i] + ko);
        }
        CP_COMMIT();
    }

    float acc[4][4][4];
    #pragma unroll
    for (int mi = 0; mi < 4; mi++)
        #pragma unroll
        for (int ni = 0; ni < 4; ni++)
            #pragma unroll
            for (int j = 0; j < 4; j++) acc[mi][ni][j] = 0.f;

    int st_load = 2, st_cmp = 0;
    for (int kt = 0; kt < NK; kt++) {
        if (kt + 2 < NK) {
            uint32_t s0 = sb + st_load * ST1;
            size_t ko = (size_t)(kt + 2) << 7;
            #pragma unroll
            for (int i = 0; i < 4; i++) {
                cp16(s0 +     0 + swo[i], (const char*)A + ga[i] + ko);
                cp16(s0 + 16384 + swo[i], (const char*)B + gb[i] + ko);
            }
            CP_COMMIT();
            if (++st_load == 3) st_load = 0;
        }
        int ahead = NK - 1 - kt; if (ahead > 2) ahead = 2;
        if (ahead == 2)      asm volatile("cp.async.wait_group 2;" ::: "memory");
        else if (ahead == 1) asm volatile("cp.async.wait_group 1;" ::: "memory");
        else                 asm volatile("cp.async.wait_group 0;" ::: "memory");
        __syncthreads();

        const uint32_t sa = sb + st_cmp * ST1;
        #pragma unroll
        for (int ks = 0; ks < 4; ks++) {
            uint32_t ah[4][4];
            const int chA = (ks << 1) + (lane >> 4);
            #pragma unroll
            for (int mi = 0; mi < 4; mi++) {
                int r = wm * 64 + mi * 16 + (lane & 15);
                uint32_t ad = sa + (uint32_t)(r * 128 + ((chA ^ (r & 7)) << 4));
                LDSM4(ah[mi], ad);
            }
            uint32_t bh[4][2];
            #pragma unroll
            for (int nb = 0; nb < 2; nb++) {
                int r = wn * 32 + nb * 16 + (lane & 15);
                uint32_t bd = sa + 16384u + (uint32_t)(r * 128 + ((chA ^ (r & 7)) << 4));
                uint32_t d[4];
                LDSM4(d, bd);
                bh[2*nb][0] = d[0];   bh[2*nb][1] = d[2];
                bh[2*nb+1][0] = d[1]; bh[2*nb+1][1] = d[3];
            }
            #pragma unroll
            for (int mi = 0; mi < 4; mi++)
                #pragma unroll
                for (int ni = 0; ni < 4; ni++)
                    MMA16816F(acc[mi][ni], ah[mi], bh[ni]);
        }
        __syncthreads();
        if (++st_cmp == 3) st_cmp = 0;
    }

    #pragma unroll
    for (int mi = 0; mi < 4; mi++) {
        int r0 = brow + wm * 64 + mi * 16 + (lane >> 2);
        #pragma unroll
        for (int ni = 0; ni < 4; ni++) {
            int c0 = bcol + wn * 32 + ni * 8 + ((lane & 3) << 1);
            *(float2*)&C[(size_t)r0 * N + c0] =
                make_float2(acc[mi][ni][0], acc[mi][ni][1]);
            *(float2*)&C[(size_t)(r0 + 8) * N + c0] =
                make_float2(acc[mi][ni][2], acc[mi][ni][3]);
        }
    }
}

// ---------------------------------------------------------------------------
// Causal depthwise conv (K=4) + SiLU (+ optional L2 norm * scale)
// ---------------------------------------------------------------------------
__global__ __launch_bounds__(128) void conv_kernel(
    const float* __restrict__ in, const float* __restrict__ w,
    float* __restrict__ out, int chans, int do_l2, float scale)
{
    const int row = blockIdx.x;
    const int c   = blockIdx.y * DHEAD + threadIdx.x;
    const int l   = row & (SEQ - 1);

    float acc = 0.f;
    #pragma unroll
    for (int j = 0; j < 4; j++) {
        int sl = l + j - 3;
        if (sl >= 0) acc += in[(size_t)(row + j - 3) * NCAT + c] * w[c * 4 + j];
    }
    float y = acc / (1.f + expf(-acc));

    if (do_l2) {
        __shared__ float sm[4];
        float ss = y * y;
        #pragma unroll
        for (int off = 16; off > 0; off >>= 1)
            ss += __shfl_xor_sync(0xffffffffu, ss, off);
        if ((threadIdx.x & 31) == 0) sm[threadIdx.x >> 5] = ss;
        __syncthreads();
        float tot = sm[0] + sm[1] + sm[2] + sm[3];
        y *= rsqrtf(tot + 1e-6f) * scale;
    }
    out[(size_t)row * chans + c] = y;
}

// ---------------------------------------------------------------------------
// Gated delta-rule recurrence, f32x2-packed, 128 CTAs.
// ---------------------------------------------------------------------------
#define FMA2(d, a, b, c) \
    asm("fma.rn.f32x2 %0, %1, %2, %3;" : "=l"(d) : "l"(a), "l"(b), "l"(c))
#define MUL2(d, a, b) \
    asm("mul.rn.f32x2 %0, %1, %2;" : "=l"(d) : "l"(a), "l"(b))

__device__ __forceinline__ unsigned long long f2pack(float a, float b) {
    unsigned long long r;
    asm("mov.b64 %0, {%1, %2};" : "=l"(r)
        : "r"(__float_as_uint(a)), "r"(__float_as_uint(b)));
    return r;
}
__device__ __forceinline__ float f2sum(unsigned long long v) {
    uint32_t x, y;
    asm("mov.b64 {%0, %1}, %2;" : "=r"(x), "=r"(y) : "l"(v));
    return __uint_as_float(x) + __uint_as_float(y);
}

__global__ __launch_bounds__(128) void recurrence_kernel()
{
    __shared__ __align__(16) float ks[2][136];
    __shared__ __align__(16) float qs[2][136];

    const int bx   = blockIdx.x;
    const int pair = bx >> 1;
    const int half = bx & 1;
    const int b  = pair >> 4;
    const int h  = pair & 15;
    const int kh = h >> 2;
    const int t  = threadIdx.x;
    const int col = half * 64 + (t >> 1);
    const int kb  = t & 1;
    const int wpos = (t < 64) ? t : t + 4;

    unsigned long long S2[32];
    #pragma unroll
    for (int d = 0; d < 32; d++) S2[d] = 0ull;

    const float* qp = g_q    + ((size_t)(b * SEQ) * NH  + h ) * DHEAD + t;
    const float* kp = g_k    + ((size_t)(b * SEQ) * NHK + kh) * DHEAD + t;
    const float* vp = g_v    + ((size_t)(b * SEQ) * NHK + kh) * DHEAD + col;
    const float* gp = g_gd   +  (size_t)(b * SEQ) * NH + h;
    const float* bp = g_beta +  (size_t)(b * SEQ) * NH + h;
    float*       op = g_o    + ((size_t)(b * SEQ) * NH  + h ) * DHEAD + col;

    float kcur = kp[0], qcur = qp[0];
    float vcur = vp[0], gcur = gp[0], bcur = bp[0];
    ks[0][wpos] = kcur; qs[0][wpos] = qcur;
    __syncthreads();

    for (int l = 0; l < SEQ; l++) {
        const int cur = l & 1, nxt = cur ^ 1;
        float knx = 0.f, qnx = 0.f, vnx = 0.f, gnx = 0.f, bnx = 0.f;
        if (l + 1 < SEQ) {
            knx = kp[(size_t)(l + 1) * 512];
            qnx = qp[(size_t)(l + 1) * 2048];
            vnx = vp[(size_t)(l + 1) * 512];
            gnx = gp[(size_t)(l + 1) * NH];
            bnx = bp[(size_t)(l + 1) * NH];
        }

        const float eg = expf(gcur);
        const unsigned long long eg2 = f2pack(eg, eg);
        const ulonglong2* k2p = reinterpret_cast<const ulonglong2*>(&ks[cur][kb * 68]);
        const ulonglong2* q2p = reinterpret_cast<const ulonglong2*>(&qs[cur][kb * 68]);

        unsigned long long kva = 0ull, kvb = 0ull;
        #pragma unroll
        for (int i = 0; i < 16; i++) {
            ulonglong2 kk = k2p[i];
            MUL2(S2[2 * i], S2[2 * i], eg2);
            FMA2(kva, kk.x, S2[2 * i], kva);
            MUL2(S2[2 * i + 1], S2[2 * i + 1], eg2);
            FMA2(kvb, kk.y, S2[2 * i + 1], kvb);
        }
        float kvp = f2sum(kva) + f2sum(kvb);
        kvp += __shfl_xor_sync(0xffffffffu, kvp, 1);
        const float cc = bcur * (vcur - kvp);
        const unsigned long long cc2 = f2pack(cc, cc);

        unsigned long long qa = 0ull, qb = 0ull;
        #pragma unroll
        for (int i = 0; i < 16; i++) {
            ulonglong2 kk = k2p[i];
            ulonglong2 qq = q2p[i];
            FMA2(S2[2 * i], kk.x, cc2, S2[2 * i]);
            FMA2(qa, qq.x, S2[2 * i], qa);
            FMA2(S2[2 * i + 1], kk.y, cc2, S2[2 * i + 1]);
            FMA2(qb, qq.y, S2[2 * i + 1], qb);
        }
        float qo = f2sum(qa) + f2sum(qb);
        qo += __shfl_xor_sync(0xffffffffu, qo, 1);
        if (kb == 0) op[(size_t)l * 2048] = qo;

        ks[nxt][wpos] = knx; qs[nxt][wpos] = qnx;
        __syncthreads();
        vcur = vnx; gcur = gnx; bcur = bnx;
    }
}

// ---------------------------------------------------------------------------
// FusedRMSNormGated -> fp16 (single rounding; gate from xcat col 3072+)
// ---------------------------------------------------------------------------
__global__ __launch_bounds__(128) void rmsgate_kernel(
    const float* __restrict__ xcat, const float* __restrict__ w)
{
    const int row = blockIdx.x;
    const int h   = blockIdx.y;
    const int t   = threadIdx.x;

    const size_t idx = (size_t)(row * NH + h) * DHEAD + t;
    float o = g_o[idx];

    float ss = o * o;
    #pragma unroll
    for (int off = 16; off > 0; off >>= 1)
        ss += __shfl_xor_sync(0xffffffffu, ss, off);
    __shared__ float sm[4];
    if ((t & 31) == 0) sm[t >> 5] = ss;
    __syncthreads();
    float tot = sm[0] + sm[1] + sm[2] + sm[3];
    float r = rsqrtf(tot * (1.f / 128.f) + 1e-5f);

    float gate = xcat[(size_t)row * NCAT + COL_G + h * DHEAD + t];
    float sg   = gate / (1.f + expf(-gate));
    float val  = o * r * w[t] * sg;
    g_of[(size_t)row * DH_ + h * DHEAD + t] = __float2half_rn(val);
}

// ---------------------------------------------------------------------------
// Launch (gemm1 stays the 4th launch -> ncu capture target)
// ---------------------------------------------------------------------------
extern "C" void kernel_launch(void* const* d_in, const int* in_sizes, int n_in,
                              void* d_out, int out_size)
{
    (void)in_sizes; (void)n_in; (void)out_size;
    const float* x     = (const float*)d_in[0];
    const float* Wq    = (const float*)d_in[1];
    const float* Wk    = (const float*)d_in[2];
    const float* Wv    = (const float*)d_in[3];
    const float* Wb    = (const float*)d_in[4];
    const float* Wgk   = (const float*)d_in[5];
    const float* A_log = (const float*)d_in[6];
    const float* dt_b  = (const float*)d_in[7];
    const float* convq = (const float*)d_in[8];
    const float* convk = (const float*)d_in[9];
    const float* convv = (const float*)d_in[10];
    const float* Wg    = (const float*)d_in[11];
    const float* onw   = (const float*)d_in[12];
    const float* Wo    = (const float*)d_in[13];
    float* out = (float*)d_out;

    cudaFuncSetAttribute(gemm1, cudaFuncAttributeMaxDynamicSharedMemorySize, SM1);
    cudaFuncSetAttribute(betag_fast, cudaFuncAttributeMaxDynamicSharedMemorySize, 65536);

    float *p_xcat, *p_q, *p_k, *p_v;
    __half *p_xhi, *p_of, *p_wcat, *p_wot;
    cudaGetSymbolAddress((void**)&p_xcat, g_xcat);
    cudaGetSymbolAddress((void**)&p_q,  g_q);
    cudaGetSymbolAddress((void**)&p_k,  g_k);
    cudaGetSymbolAddress((void**)&p_v,  g_v);
    cudaGetSymbolAddress((void**)&p_xhi, g_xhi);
    cudaGetSymbolAddress((void**)&p_of,  g_of);
    cudaGetSymbolAddress((void**)&p_wcat, g_wcat);
    cudaGetSymbolAddress((void**)&p_wot,  g_wot);

    // 1) x -> fp16
    tof16_kernel<<<(ROWS * DH_ / 2 + 255) / 256, 256>>>(x, p_xhi, ROWS * DH_ / 2);
    // 2) all weight transposes (fused)
    transpose_all<<<14336, 256>>>(Wq, Wk, Wv, Wg, Wo, p_wcat, p_wot);
    // 3) exact fp32 beta/g (thin GEMM)
    betag_fast<<<ROWS / 8, 256, 65536>>>(x, Wb, Wgk, A_log, dt_b);
    // 4) fused projection GEMM   <-- ncu capture target
    gemm1<<<dim3(NCAT / 128, 32), 256, SM1>>>(p_xhi, p_wcat, p_xcat, NCAT, DH_);
    // 5-7) conv + silu (+ l2 norm; q scaled by D^-0.5)
    conv_kernel<<<dim3(ROWS, 16), 128>>>(p_xcat,         convq, p_q, 2048, 1, 0.08838834764831845f);
    conv_kernel<<<dim3(ROWS,  4), 128>>>(p_xcat + COL_K, convk, p_k,  512, 1, 1.f);
    conv_kernel<<<dim3(ROWS,  4), 128>>>(p_xcat + COL_V, convv, p_v,  512, 0, 1.f);
    // 8) recurrence
    recurrence_kernel<<<128, 128>>>();
    // 9) gated rmsnorm (-> fp16)
    rmsgate_kernel<<<dim3(ROWS, 16), 128>>>(p_xcat, onw);
    // 10) output projection (1-pass fp16)
    gemm1<<<dim3(16, 32), 256, SM1>>>(p_of, p_wot, out, 2048, DH_);
}